// round 1
// baseline (speedup 1.0000x reference)
#include <cuda_runtime.h>

// ---------------------------------------------------------------------------
// Problem constants
// ---------------------------------------------------------------------------
#define NB    16          // batch
#define NPTS  512         // points per cloud
#define BNT   (NB*NPTS)   // 8192
#define KNN   8
#define SEQ   12
#define HALF  6

// ---------------------------------------------------------------------------
// Scratch (static device globals: no runtime allocation allowed)
// ---------------------------------------------------------------------------
__device__ float g_f1[2 * BNT * 64];    // cell1 feat ping-pong
__device__ float g_f2[2 * BNT * 128];   // cell2 feat ping-pong
__device__ float g_f3[2 * BNT * 256];   // cell3 feat ping-pong
__device__ float g_Y1[BNT * 64];
__device__ float g_Y2[BNT * 128];
__device__ float g_Y3[BNT * 256];
__device__ float g_Q2[BNT * 128];
__device__ float g_Q3[BNT * 256];
__device__ float g_G [BNT * 64];        // feat3 @ Wm (pre-bias, pre-relu)
__device__ int   g_idx[BNT * KNN];
__device__ float g_d2 [BNT * KNN];

// ---------------------------------------------------------------------------
// zero the parity-0 state buffers (state at t=0 is zeros)
// ---------------------------------------------------------------------------
__global__ void zero_states()
{
    int stride = gridDim.x * blockDim.x;
    int i0 = blockIdx.x * blockDim.x + threadIdx.x;
    for (int i = i0; i < BNT * 64;  i += stride) g_f1[i] = 0.f;
    for (int i = i0; i < BNT * 128; i += stride) g_f2[i] = 0.f;
    for (int i = i0; i < BNT * 256; i += stride) g_f3[i] = 0.f;
}

// ---------------------------------------------------------------------------
// top-8 nearest neighbors (shared across all 3 cells of a timestep)
// query xyz (b,n): q[b*qbs + n*3 + d]; source xyz: s[b*sbs + j*3 + d]
// Tie-break: strictly-smaller d2 wins; equal d2 keeps lower index first
// (matches jax.lax.top_k stability since we scan ascending j).
// ---------------------------------------------------------------------------
__global__ __launch_bounds__(128) void topk_kernel(
    const float* __restrict__ q, int qbs,
    const float* __restrict__ s, int sbs,
    int*   __restrict__ idxOut,
    float* __restrict__ d2Out)
{
    __shared__ float sx[NPTS], sy[NPTS], sz[NPTS];
    int b  = blockIdx.x >> 2;            // 4 blocks of 128 threads per batch
    int n0 = (blockIdx.x & 3) * 128;

    const float* sb = s + b * sbs;
    for (int i = threadIdx.x; i < NPTS; i += 128) {
        sx[i] = sb[i*3 + 0];
        sy[i] = sb[i*3 + 1];
        sz[i] = sb[i*3 + 2];
    }
    __syncthreads();

    int n = n0 + threadIdx.x;
    const float* qp = q + b * qbs + n * 3;
    float qx = qp[0], qy = qp[1], qz = qp[2];

    float bd[KNN]; int bi[KNN];
    #pragma unroll
    for (int k = 0; k < KNN; k++) { bd[k] = 3.4e38f; bi[k] = 0; }

    for (int j = 0; j < NPTS; j++) {
        float dx = __fadd_rn(qx, -sx[j]);
        float dy = __fadd_rn(qy, -sy[j]);
        float dz = __fadd_rn(qz, -sz[j]);
        // unfused mul/add to match XLA elementwise square + reduce rounding
        float d = __fadd_rn(__fadd_rn(__fmul_rn(dx, dx), __fmul_rn(dy, dy)),
                            __fmul_rn(dz, dz));
        if (d < bd[KNN-1]) {
            bd[KNN-1] = d; bi[KNN-1] = j;
            #pragma unroll
            for (int t = KNN-1; t > 0; --t) {
                if (bd[t] < bd[t-1]) {
                    float td = bd[t]; bd[t] = bd[t-1]; bd[t-1] = td;
                    int   ti = bi[t]; bi[t] = bi[t-1]; bi[t-1] = ti;
                }
            }
        }
    }

    int base = (b * NPTS + n) * KNN;
    #pragma unroll
    for (int k = 0; k < KNN; k++) {
        idxOut[base + k] = bi[k];
        d2Out [base + k] = bd[k];
    }
}

// ---------------------------------------------------------------------------
// Tiled SGEMM: C[M=8192, N] = A[M, K] @ B[K, N]   (B row stride == N)
// 64x64 block tile, BK=32, 256 threads, 4x4 per thread.
// Up to 3 independent problems batched over blockIdx.z.
// ---------------------------------------------------------------------------
struct GemmP {
    const float* A;
    const float* B;
    float*       C;
    int N;
    int K;
};

__global__ __launch_bounds__(256) void gemm_kernel(GemmP p0, GemmP p1, GemmP p2)
{
    GemmP p = (blockIdx.z == 0) ? p0 : (blockIdx.z == 1) ? p1 : p2;
    int nOff = blockIdx.y * 64;
    if (nOff >= p.N) return;

    __shared__ __align__(16) float As[32][65];   // [k][m], padded: conflict-free
    __shared__ __align__(16) float Bs[32][64];   // [k][n]

    int tid = threadIdx.x;
    int tx = tid & 15, ty = tid >> 4;

    const float* A = p.A + (blockIdx.x * 64) * p.K;
    const float* B = p.B + nOff;

    float acc[4][4] = {};

    int cA  = tid & 31;   // k-col for A loads
    int rA0 = tid >> 5;   // 0..7
    int cB  = tid & 63;   // n-col for B loads
    int rB0 = tid >> 6;   // 0..3

    for (int k0 = 0; k0 < p.K; k0 += 32) {
        #pragma unroll
        for (int i = 0; i < 8; i++) {
            int r = rA0 + i * 8;                     // m row 0..63
            As[cA][r] = A[r * p.K + k0 + cA];
        }
        #pragma unroll
        for (int i = 0; i < 8; i++) {
            int r = rB0 + i * 4;                     // k row 0..31
            Bs[r][cB] = B[(k0 + r) * p.N + cB];
        }
        __syncthreads();

        #pragma unroll
        for (int k = 0; k < 32; k++) {
            float a0 = As[k][ty*4 + 0];
            float a1 = As[k][ty*4 + 1];
            float a2 = As[k][ty*4 + 2];
            float a3 = As[k][ty*4 + 3];
            float4 bv = *reinterpret_cast<const float4*>(&Bs[k][tx*4]);
            acc[0][0] += a0 * bv.x; acc[0][1] += a0 * bv.y;
            acc[0][2] += a0 * bv.z; acc[0][3] += a0 * bv.w;
            acc[1][0] += a1 * bv.x; acc[1][1] += a1 * bv.y;
            acc[1][2] += a1 * bv.z; acc[1][3] += a1 * bv.w;
            acc[2][0] += a2 * bv.x; acc[2][1] += a2 * bv.y;
            acc[2][2] += a2 * bv.z; acc[2][3] += a2 * bv.w;
            acc[3][0] += a3 * bv.x; acc[3][1] += a3 * bv.y;
            acc[3][2] += a3 * bv.z; acc[3][3] += a3 * bv.w;
        }
        __syncthreads();
    }

    float* C = p.C + (blockIdx.x * 64 + ty * 4) * p.N + nOff + tx * 4;
    #pragma unroll
    for (int i = 0; i < 4; i++)
        #pragma unroll
        for (int j = 0; j < 4; j++)
            C[i * p.N + j] = acc[i][j];
}

// ---------------------------------------------------------------------------
// combine: out[p, j] = bias[j] + Q[p,j] + max_k( Y[row_k, j] + disp_k . Wd[:,j] )
// row_k = b*512 + (d2_k <= r2 ? idx_k : idx_0)
// W points at full weight matrix base (rows 0..2 are the disp rows), stride C.
// ---------------------------------------------------------------------------
__global__ void combine_kernel(
    const float* __restrict__ Y,
    const float* __restrict__ Q,       // may be nullptr (cell 1)
    const float* __restrict__ W,
    const float* __restrict__ bias,
    const int*   __restrict__ idx,
    const float* __restrict__ d2,
    const float* __restrict__ qx, int qbs,
    const float* __restrict__ sx, int sbs,
    float r2,
    float* __restrict__ outF,
    int C)
{
    __shared__ int   sRow [4][KNN];
    __shared__ float sDisp[4][KNN][3];

    int p = blockIdx.x * blockDim.y + threadIdx.y;
    int b = p >> 9, n = p & 511;
    int j = threadIdx.x;

    if (j < KNN) {
        int   raw = idx[p * KNN + j];
        int   i0  = idx[p * KNN];
        float dd  = d2 [p * KNN + j];
        int eff = (dd <= r2) ? raw : i0;
        sRow[threadIdx.y][j] = b * NPTS + eff;
        const float* sp = sx + b * sbs + eff * 3;
        const float* qp = qx + b * qbs + n   * 3;
        sDisp[threadIdx.y][j][0] = sp[0] - qp[0];
        sDisp[threadIdx.y][j][1] = sp[1] - qp[1];
        sDisp[threadIdx.y][j][2] = sp[2] - qp[2];
    }
    __syncthreads();

    float w0 = W[j], w1 = W[C + j], w2 = W[2*C + j];
    float base = bias[j] + (Q ? Q[p * C + j] : 0.f);

    float m = -3.4e38f;
    #pragma unroll
    for (int k = 0; k < KNN; k++) {
        int row = sRow[threadIdx.y][k];
        float v = Y[row * C + j]
                + sDisp[threadIdx.y][k][0] * w0
                + sDisp[threadIdx.y][k][1] * w1
                + sDisp[threadIdx.y][k][2] * w2;
        m = fmaxf(m, v);
    }
    outF[p * C + j] = base + m;
}

// ---------------------------------------------------------------------------
// motion MLP tail: h = relu(G + bm); motion = h @ Wl + bl; dst = cur + motion
// ---------------------------------------------------------------------------
__global__ __launch_bounds__(256) void mlp_tail(
    const float* __restrict__ G,
    const float* __restrict__ bm,
    const float* __restrict__ Wl,
    const float* __restrict__ bl,
    const float* __restrict__ cur, int cbs,
    float* __restrict__ dst, int dbs)
{
    __shared__ float sWl[64 * 3];
    __shared__ float sbm[64];
    __shared__ float sbl[3];
    if (threadIdx.x < 192) sWl[threadIdx.x] = Wl[threadIdx.x];
    if (threadIdx.x < 64)  sbm[threadIdx.x] = bm[threadIdx.x];
    if (threadIdx.x < 3)   sbl[threadIdx.x] = bl[threadIdx.x];
    __syncthreads();

    int p = blockIdx.x * blockDim.x + threadIdx.x;
    float m0 = sbl[0], m1 = sbl[1], m2 = sbl[2];
    const float* g = G + p * 64;
    #pragma unroll
    for (int jj = 0; jj < 64; jj++) {
        float h = fmaxf(g[jj] + sbm[jj], 0.f);
        m0 += h * sWl[jj*3 + 0];
        m1 += h * sWl[jj*3 + 1];
        m2 += h * sWl[jj*3 + 2];
    }
    int b = p >> 9, n = p & 511;
    const float* cp = cur + b * cbs + n * 3;
    float*       dp = dst + b * dbs + n * 3;
    dp[0] = cp[0] + m0;
    dp[1] = cp[1] + m1;
    dp[2] = cp[2] + m2;
}

// ---------------------------------------------------------------------------
// host orchestration
// ---------------------------------------------------------------------------
extern "C" void kernel_launch(void* const* d_in, const int* in_sizes, int n_in,
                              void* d_out, int out_size)
{
    (void)in_sizes; (void)n_in; (void)out_size;

    const float* frames = (const float*)d_in[0];
    const float* W1 = (const float*)d_in[1];
    const float* b1 = (const float*)d_in[2];
    const float* W2 = (const float*)d_in[3];
    const float* b2 = (const float*)d_in[4];
    const float* W3 = (const float*)d_in[5];
    const float* b3 = (const float*)d_in[6];
    const float* Wm = (const float*)d_in[7];
    const float* bm = (const float*)d_in[8];
    const float* Wl = (const float*)d_in[9];
    const float* bl = (const float*)d_in[10];
    float* out = (float*)d_out;

    float *f1, *f2, *f3, *Y1, *Y2, *Y3, *Q2, *Q3, *G;
    int* idxp; float* d2p;
    { void* t;
      cudaGetSymbolAddress(&t, g_f1); f1 = (float*)t;
      cudaGetSymbolAddress(&t, g_f2); f2 = (float*)t;
      cudaGetSymbolAddress(&t, g_f3); f3 = (float*)t;
      cudaGetSymbolAddress(&t, g_Y1); Y1 = (float*)t;
      cudaGetSymbolAddress(&t, g_Y2); Y2 = (float*)t;
      cudaGetSymbolAddress(&t, g_Y3); Y3 = (float*)t;
      cudaGetSymbolAddress(&t, g_Q2); Q2 = (float*)t;
      cudaGetSymbolAddress(&t, g_Q3); Q3 = (float*)t;
      cudaGetSymbolAddress(&t, g_G);  G  = (float*)t;
      cudaGetSymbolAddress(&t, g_idx); idxp = (int*)t;
      cudaGetSymbolAddress(&t, g_d2);  d2p  = (float*)t;
    }

    const int FBS = SEQ * NPTS * 3;   // frames batch stride (18432)
    const int OBS = HALF * NPTS * 3;  // output batch stride (9216)
    const int FRM = NPTS * 3;         // one frame within a batch (1536)

    const double R0 = 4.0 + 1e-6, R1 = 8.0 + 1e-6, R2 = 12.0 + 1e-6;
    const float r2c1 = (float)(R0 * R0);
    const float r2c2 = (float)(R1 * R1);
    const float r2c3 = (float)(R2 * R2);

    // weight sub-block pointers (row-major (cin, cout))
    const float* Wn1 = W1 + 3 * 64;           // rows 3..66
    const float* Wf2 = W2 + 3 * 128;          // rows 3..66
    const float* Wn2 = W2 + (3 + 64) * 128;   // rows 67..194
    const float* Wf3 = W3 + 3 * 256;          // rows 3..130
    const float* Wn3 = W3 + (3 + 128) * 256;  // rows 131..386

    zero_states<<<256, 256>>>();

    for (int t = 0; t < SEQ; t++) {
        const float *q, *s; int qbs, sbs;
        if (t < HALF) {
            q = frames + t * FRM;                       qbs = FBS;
            s = frames + (t ? (t - 1) : 0) * FRM;       sbs = FBS;
        } else if (t == HALF) {           // query = input_frame = F5, state = F5
            q = frames + (HALF - 1) * FRM;              qbs = FBS;
            s = q;                                      sbs = FBS;
        } else if (t == HALF + 1) {       // query = pred0, state = F5
            q = out;                                    qbs = OBS;
            s = frames + (HALF - 1) * FRM;              sbs = FBS;
        } else {
            q = out + (t - HALF - 1) * FRM;             qbs = OBS;
            s = out + (t - HALF - 2) * FRM;             sbs = OBS;
        }

        int pin = t & 1, pout = 1 - pin;
        float* f1i = f1 + pin  * BNT * 64;
        float* f1o = f1 + pout * BNT * 64;
        float* f2i = f2 + pin  * BNT * 128;
        float* f2o = f2 + pout * BNT * 128;
        float* f3i = f3 + pin  * BNT * 256;
        float* f3o = f3 + pout * BNT * 256;

        // 1) shared top-8 neighbor search
        topk_kernel<<<64, 128>>>(q, qbs, s, sbs, idxp, d2p);

        // 2) Y GEMMs for all 3 cells (depend only on previous-step state)
        GemmP y1 = { f1i, Wn1, Y1, 64, 64 };
        GemmP y2 = { f2i, Wn2, Y2, 128, 128 };
        GemmP y3 = { f3i, Wn3, Y3, 256, 256 };
        gemm_kernel<<<dim3(128, 4, 3), 256>>>(y1, y2, y3);

        // 3) cell 1 combine (no Q)
        combine_kernel<<<BNT / 4, dim3(64, 4)>>>(
            Y1, nullptr, W1, b1, idxp, d2p, q, qbs, s, sbs, r2c1, f1o, 64);

        // 4) cell 2: Q2 = f1o @ Wf2, then combine
        GemmP q2d = { f1o, Wf2, Q2, 128, 64 };
        gemm_kernel<<<dim3(128, 2, 1), 256>>>(q2d, q2d, q2d);
        combine_kernel<<<BNT / 2, dim3(128, 2)>>>(
            Y2, Q2, W2, b2, idxp, d2p, q, qbs, s, sbs, r2c2, f2o, 128);

        // 5) cell 3: Q3 = f2o @ Wf3, then combine
        GemmP q3d = { f2o, Wf3, Q3, 256, 128 };
        gemm_kernel<<<dim3(128, 4, 1), 256>>>(q3d, q3d, q3d);
        combine_kernel<<<BNT, dim3(256, 1)>>>(
            Y3, Q3, W3, b3, idxp, d2p, q, qbs, s, sbs, r2c3, f3o, 256);

        // 6) prediction steps: motion MLP, frame update, write output slot
        if (t >= HALF) {
            GemmP gm = { f3o, Wm, G, 64, 256 };
            gemm_kernel<<<dim3(128, 1, 1), 256>>>(gm, gm, gm);
            mlp_tail<<<BNT / 256, 256>>>(G, bm, Wl, bl, q, qbs,
                                         out + (t - HALF) * FRM, OBS);
        }
    }
}

// round 2
// speedup vs baseline: 1.1005x; 1.1005x over previous
#include <cuda_runtime.h>

// ---------------------------------------------------------------------------
// Problem constants
// ---------------------------------------------------------------------------
#define NB    16          // batch
#define NPTS  512         // points per cloud
#define BNT   (NB*NPTS)   // 8192
#define KNN   8
#define SEQ   12
#define HALF  6

// ---------------------------------------------------------------------------
// Scratch (static device globals: no runtime allocation allowed)
// ---------------------------------------------------------------------------
__device__ float g_f1[2 * BNT * 64];    // cell1 feat ping-pong
__device__ float g_f2[2 * BNT * 128];   // cell2 feat ping-pong
__device__ float g_f3[2 * BNT * 256];   // cell3 feat ping-pong
__device__ float g_Y1[BNT * 64];
__device__ float g_Y2[BNT * 128];
__device__ float g_Y3[BNT * 256];
__device__ float g_Q2[BNT * 128];
__device__ float g_Q3[BNT * 256];
__device__ float g_G [BNT * 64];        // feat3 @ Wm (pre-bias, pre-relu)
__device__ int   g_idx[BNT * KNN];
__device__ float g_d2 [BNT * KNN];

// ---------------------------------------------------------------------------
// packed f32x2 helpers (SASS FFMA2 — ptxas never emits these from C++)
// ---------------------------------------------------------------------------
__device__ __forceinline__ unsigned long long dup2(float x)
{
    unsigned long long r;
    asm("mov.b64 %0, {%1, %1};" : "=l"(r) : "f"(x));
    return r;
}
__device__ __forceinline__ void ffma2(unsigned long long& d,
                                      unsigned long long a,
                                      unsigned long long b)
{
    asm("fma.rn.f32x2 %0, %1, %2, %0;" : "+l"(d) : "l"(a), "l"(b));
}
__device__ __forceinline__ float2 unpk(unsigned long long v)
{
    float2 f;
    asm("mov.b64 {%0, %1}, %2;" : "=f"(f.x), "=f"(f.y) : "l"(v));
    return f;
}

// ---------------------------------------------------------------------------
// zero the parity-0 state buffers (state at t=0 is zeros)
// ---------------------------------------------------------------------------
__global__ void zero_states()
{
    int stride = gridDim.x * blockDim.x;
    int i0 = blockIdx.x * blockDim.x + threadIdx.x;
    for (int i = i0; i < BNT * 64;  i += stride) g_f1[i] = 0.f;
    for (int i = i0; i < BNT * 128; i += stride) g_f2[i] = 0.f;
    for (int i = i0; i < BNT * 256; i += stride) g_f3[i] = 0.f;
}

// ---------------------------------------------------------------------------
// top-8 nearest neighbors (shared across all 3 cells of a timestep)
// 128 blocks x 64 threads: one query point per thread, full source in smem.
// Tie-break: strictly-smaller d2 wins; equal d2 keeps lower index first
// (matches jax.lax.top_k stability since we scan ascending j).
// ---------------------------------------------------------------------------
__global__ __launch_bounds__(64) void topk_kernel(
    const float* __restrict__ q, int qbs,
    const float* __restrict__ s, int sbs,
    int*   __restrict__ idxOut,
    float* __restrict__ d2Out)
{
    __shared__ float sx[NPTS], sy[NPTS], sz[NPTS];
    int b  = blockIdx.x >> 3;            // 8 blocks of 64 threads per batch
    int n0 = (blockIdx.x & 7) * 64;

    const float* sb = s + b * sbs;
    for (int i = threadIdx.x; i < NPTS; i += 64) {
        sx[i] = sb[i*3 + 0];
        sy[i] = sb[i*3 + 1];
        sz[i] = sb[i*3 + 2];
    }
    __syncthreads();

    int n = n0 + threadIdx.x;
    const float* qp = q + b * qbs + n * 3;
    float qx = qp[0], qy = qp[1], qz = qp[2];

    float bd[KNN]; int bi[KNN];
    #pragma unroll
    for (int k = 0; k < KNN; k++) { bd[k] = 3.4e38f; bi[k] = 0; }

    for (int j = 0; j < NPTS; j++) {
        float dx = __fadd_rn(qx, -sx[j]);
        float dy = __fadd_rn(qy, -sy[j]);
        float dz = __fadd_rn(qz, -sz[j]);
        // unfused mul/add to match XLA elementwise square + reduce rounding
        float d = __fadd_rn(__fadd_rn(__fmul_rn(dx, dx), __fmul_rn(dy, dy)),
                            __fmul_rn(dz, dz));
        if (d < bd[KNN-1]) {
            bd[KNN-1] = d; bi[KNN-1] = j;
            #pragma unroll
            for (int t = KNN-1; t > 0; --t) {
                if (bd[t] < bd[t-1]) {
                    float td = bd[t]; bd[t] = bd[t-1]; bd[t-1] = td;
                    int   ti = bi[t]; bi[t] = bi[t-1]; bi[t-1] = ti;
                }
            }
        }
    }

    int base = (b * NPTS + n) * KNN;
    #pragma unroll
    for (int k = 0; k < KNN; k++) {
        idxOut[base + k] = bi[k];
        d2Out [base + k] = bd[k];
    }
}

// ---------------------------------------------------------------------------
// Packed-f32x2 SGEMM: C[M=8192, N] = A[M, K] @ B[K, N]  (B row stride == N)
// 64x64 block tile, BK=32, 128 threads, 8(m)x4(n) per thread.
// Accumulators packed along m -> A pairs load directly as LDS.64;
// only B scalars need lane duplication (1 mov per FFMA2 pair of columns).
// Up to 3 independent problems batched over blockIdx.z.
// ---------------------------------------------------------------------------
struct GemmP {
    const float* A;
    const float* B;
    float*       C;
    int N;
    int K;
};

__global__ __launch_bounds__(128) void gemm_kernel(GemmP p0, GemmP p1, GemmP p2)
{
    GemmP p = (blockIdx.z == 0) ? p0 : (blockIdx.z == 1) ? p1 : p2;
    int nOff = blockIdx.y * 64;
    if (nOff >= p.N) return;

    __shared__ __align__(16) float As[32][66];   // [k][m] (stride 66: 8B-aligned rows)
    __shared__ __align__(16) float Bs[32][64];   // [k][n]

    int tid = threadIdx.x;
    int tx = tid & 15;        // n group (4 cols)
    int ty = tid >> 4;        // m group (8 rows)

    const float* A = p.A + (blockIdx.x * 64) * p.K;
    const float* B = p.B + nOff;

    unsigned long long acc[4][4];     // [m-pair][n]
    #pragma unroll
    for (int i = 0; i < 4; i++)
        #pragma unroll
        for (int j = 0; j < 4; j++) acc[i][j] = 0ull;

    int cA  = tid & 31;   // k-col for A loads
    int rA0 = tid >> 5;   // 0..3
    int cB  = tid & 63;   // n-col for B loads
    int rB0 = tid >> 6;   // 0..1

    for (int k0 = 0; k0 < p.K; k0 += 32) {
        #pragma unroll
        for (int i = 0; i < 16; i++) {
            int r = rA0 + i * 4;                 // m row 0..63
            As[cA][r] = A[r * p.K + k0 + cA];
        }
        #pragma unroll
        for (int i = 0; i < 16; i++) {
            int r = rB0 + i * 2;                 // k row 0..31
            Bs[r][cB] = B[(k0 + r) * p.N + cB];
        }
        __syncthreads();

        #pragma unroll
        for (int k = 0; k < 32; k++) {
            unsigned long long a0 = *reinterpret_cast<const unsigned long long*>(&As[k][ty*8 + 0]);
            unsigned long long a1 = *reinterpret_cast<const unsigned long long*>(&As[k][ty*8 + 2]);
            unsigned long long a2 = *reinterpret_cast<const unsigned long long*>(&As[k][ty*8 + 4]);
            unsigned long long a3 = *reinterpret_cast<const unsigned long long*>(&As[k][ty*8 + 6]);
            float4 bv = *reinterpret_cast<const float4*>(&Bs[k][tx*4]);
            unsigned long long b0 = dup2(bv.x);
            unsigned long long b1 = dup2(bv.y);
            unsigned long long b2 = dup2(bv.z);
            unsigned long long b3 = dup2(bv.w);
            ffma2(acc[0][0], a0, b0); ffma2(acc[0][1], a0, b1);
            ffma2(acc[0][2], a0, b2); ffma2(acc[0][3], a0, b3);
            ffma2(acc[1][0], a1, b0); ffma2(acc[1][1], a1, b1);
            ffma2(acc[1][2], a1, b2); ffma2(acc[1][3], a1, b3);
            ffma2(acc[2][0], a2, b0); ffma2(acc[2][1], a2, b1);
            ffma2(acc[2][2], a2, b2); ffma2(acc[2][3], a2, b3);
            ffma2(acc[3][0], a3, b0); ffma2(acc[3][1], a3, b1);
            ffma2(acc[3][2], a3, b2); ffma2(acc[3][3], a3, b3);
        }
        __syncthreads();
    }

    float* C = p.C + (blockIdx.x * 64 + ty * 8) * p.N + nOff + tx * 4;
    #pragma unroll
    for (int pm = 0; pm < 4; pm++) {
        float2 u0 = unpk(acc[pm][0]);
        float2 u1 = unpk(acc[pm][1]);
        float2 u2 = unpk(acc[pm][2]);
        float2 u3 = unpk(acc[pm][3]);
        float4 lo = make_float4(u0.x, u1.x, u2.x, u3.x);
        float4 hi = make_float4(u0.y, u1.y, u2.y, u3.y);
        *reinterpret_cast<float4*>(C + (pm*2 + 0) * p.N) = lo;
        *reinterpret_cast<float4*>(C + (pm*2 + 1) * p.N) = hi;
    }
}

// ---------------------------------------------------------------------------
// combine: out[p, j] = bias[j] + Q[p,j] + max_k( Y[row_k, j] + disp_k . Wd[:,j] )
// row_k = b*512 + (d2_k <= r2 ? idx_k : idx_0)
// W points at full weight matrix base (rows 0..2 are the disp rows), stride C.
// ---------------------------------------------------------------------------
__global__ void combine_kernel(
    const float* __restrict__ Y,
    const float* __restrict__ Q,       // may be nullptr (cell 1)
    const float* __restrict__ W,
    const float* __restrict__ bias,
    const int*   __restrict__ idx,
    const float* __restrict__ d2,
    const float* __restrict__ qx, int qbs,
    const float* __restrict__ sx, int sbs,
    float r2,
    float* __restrict__ outF,
    int C)
{
    __shared__ int   sRow [4][KNN];
    __shared__ float sDisp[4][KNN][3];

    int p = blockIdx.x * blockDim.y + threadIdx.y;
    int b = p >> 9, n = p & 511;
    int j = threadIdx.x;

    if (j < KNN) {
        int   raw = idx[p * KNN + j];
        int   i0  = idx[p * KNN];
        float dd  = d2 [p * KNN + j];
        int eff = (dd <= r2) ? raw : i0;
        sRow[threadIdx.y][j] = b * NPTS + eff;
        const float* sp = sx + b * sbs + eff * 3;
        const float* qp = qx + b * qbs + n   * 3;
        sDisp[threadIdx.y][j][0] = sp[0] - qp[0];
        sDisp[threadIdx.y][j][1] = sp[1] - qp[1];
        sDisp[threadIdx.y][j][2] = sp[2] - qp[2];
    }
    __syncthreads();

    float w0 = W[j], w1 = W[C + j], w2 = W[2*C + j];
    float base = bias[j] + (Q ? Q[p * C + j] : 0.f);

    float m = -3.4e38f;
    #pragma unroll
    for (int k = 0; k < KNN; k++) {
        int row = sRow[threadIdx.y][k];
        float v = Y[row * C + j]
                + sDisp[threadIdx.y][k][0] * w0
                + sDisp[threadIdx.y][k][1] * w1
                + sDisp[threadIdx.y][k][2] * w2;
        m = fmaxf(m, v);
    }
    outF[p * C + j] = base + m;
}

// ---------------------------------------------------------------------------
// motion MLP tail: h = relu(G + bm); motion = h @ Wl + bl; dst = cur + motion
// ---------------------------------------------------------------------------
__global__ __launch_bounds__(256) void mlp_tail(
    const float* __restrict__ G,
    const float* __restrict__ bm,
    const float* __restrict__ Wl,
    const float* __restrict__ bl,
    const float* __restrict__ cur, int cbs,
    float* __restrict__ dst, int dbs)
{
    __shared__ float sWl[64 * 3];
    __shared__ float sbm[64];
    __shared__ float sbl[3];
    if (threadIdx.x < 192) sWl[threadIdx.x] = Wl[threadIdx.x];
    if (threadIdx.x < 64)  sbm[threadIdx.x] = bm[threadIdx.x];
    if (threadIdx.x < 3)   sbl[threadIdx.x] = bl[threadIdx.x];
    __syncthreads();

    int p = blockIdx.x * blockDim.x + threadIdx.x;
    float m0 = sbl[0], m1 = sbl[1], m2 = sbl[2];
    const float* g = G + p * 64;
    #pragma unroll
    for (int jj = 0; jj < 64; jj++) {
        float h = fmaxf(g[jj] + sbm[jj], 0.f);
        m0 += h * sWl[jj*3 + 0];
        m1 += h * sWl[jj*3 + 1];
        m2 += h * sWl[jj*3 + 2];
    }
    int b = p >> 9, n = p & 511;
    const float* cp = cur + b * cbs + n * 3;
    float*       dp = dst + b * dbs + n * 3;
    dp[0] = cp[0] + m0;
    dp[1] = cp[1] + m1;
    dp[2] = cp[2] + m2;
}

// ---------------------------------------------------------------------------
// host orchestration
// ---------------------------------------------------------------------------
extern "C" void kernel_launch(void* const* d_in, const int* in_sizes, int n_in,
                              void* d_out, int out_size)
{
    (void)in_sizes; (void)n_in; (void)out_size;

    const float* frames = (const float*)d_in[0];
    const float* W1 = (const float*)d_in[1];
    const float* b1 = (const float*)d_in[2];
    const float* W2 = (const float*)d_in[3];
    const float* b2 = (const float*)d_in[4];
    const float* W3 = (const float*)d_in[5];
    const float* b3 = (const float*)d_in[6];
    const float* Wm = (const float*)d_in[7];
    const float* bm = (const float*)d_in[8];
    const float* Wl = (const float*)d_in[9];
    const float* bl = (const float*)d_in[10];
    float* out = (float*)d_out;

    float *f1, *f2, *f3, *Y1, *Y2, *Y3, *Q2, *Q3, *G;
    int* idxp; float* d2p;
    { void* t;
      cudaGetSymbolAddress(&t, g_f1); f1 = (float*)t;
      cudaGetSymbolAddress(&t, g_f2); f2 = (float*)t;
      cudaGetSymbolAddress(&t, g_f3); f3 = (float*)t;
      cudaGetSymbolAddress(&t, g_Y1); Y1 = (float*)t;
      cudaGetSymbolAddress(&t, g_Y2); Y2 = (float*)t;
      cudaGetSymbolAddress(&t, g_Y3); Y3 = (float*)t;
      cudaGetSymbolAddress(&t, g_Q2); Q2 = (float*)t;
      cudaGetSymbolAddress(&t, g_Q3); Q3 = (float*)t;
      cudaGetSymbolAddress(&t, g_G);  G  = (float*)t;
      cudaGetSymbolAddress(&t, g_idx); idxp = (int*)t;
      cudaGetSymbolAddress(&t, g_d2);  d2p  = (float*)t;
    }

    const int FBS = SEQ * NPTS * 3;   // frames batch stride (18432)
    const int OBS = HALF * NPTS * 3;  // output batch stride (9216)
    const int FRM = NPTS * 3;         // one frame within a batch (1536)

    const double R0 = 4.0 + 1e-6, R1 = 8.0 + 1e-6, R2 = 12.0 + 1e-6;
    const float r2c1 = (float)(R0 * R0);
    const float r2c2 = (float)(R1 * R1);
    const float r2c3 = (float)(R2 * R2);

    // weight sub-block pointers (row-major (cin, cout))
    const float* Wn1 = W1 + 3 * 64;           // rows 3..66
    const float* Wf2 = W2 + 3 * 128;          // rows 3..66
    const float* Wn2 = W2 + (3 + 64) * 128;   // rows 67..194
    const float* Wf3 = W3 + 3 * 256;          // rows 3..130
    const float* Wn3 = W3 + (3 + 128) * 256;  // rows 131..386

    zero_states<<<256, 256>>>();

    for (int t = 0; t < SEQ; t++) {
        const float *q, *s; int qbs, sbs;
        if (t < HALF) {
            q = frames + t * FRM;                       qbs = FBS;
            s = frames + (t ? (t - 1) : 0) * FRM;       sbs = FBS;
        } else if (t == HALF) {           // query = input_frame = F5, state = F5
            q = frames + (HALF - 1) * FRM;              qbs = FBS;
            s = q;                                      sbs = FBS;
        } else if (t == HALF + 1) {       // query = pred0, state = F5
            q = out;                                    qbs = OBS;
            s = frames + (HALF - 1) * FRM;              sbs = FBS;
        } else {
            q = out + (t - HALF - 1) * FRM;             qbs = OBS;
            s = out + (t - HALF - 2) * FRM;             sbs = OBS;
        }

        int pin = t & 1, pout = 1 - pin;
        float* f1i = f1 + pin  * BNT * 64;
        float* f1o = f1 + pout * BNT * 64;
        float* f2i = f2 + pin  * BNT * 128;
        float* f2o = f2 + pout * BNT * 128;
        float* f3i = f3 + pin  * BNT * 256;
        float* f3o = f3 + pout * BNT * 256;

        // 1) shared top-8 neighbor search
        topk_kernel<<<128, 64>>>(q, qbs, s, sbs, idxp, d2p);

        // 2) Y GEMMs for all 3 cells (depend only on previous-step state)
        GemmP y1 = { f1i, Wn1, Y1, 64, 64 };
        GemmP y2 = { f2i, Wn2, Y2, 128, 128 };
        GemmP y3 = { f3i, Wn3, Y3, 256, 256 };
        gemm_kernel<<<dim3(128, 4, 3), 128>>>(y1, y2, y3);

        // 3) cell 1 combine (no Q)
        combine_kernel<<<BNT / 4, dim3(64, 4)>>>(
            Y1, nullptr, W1, b1, idxp, d2p, q, qbs, s, sbs, r2c1, f1o, 64);

        // 4) cell 2: Q2 = f1o @ Wf2, then combine
        GemmP q2d = { f1o, Wf2, Q2, 128, 64 };
        gemm_kernel<<<dim3(128, 2, 1), 128>>>(q2d, q2d, q2d);
        combine_kernel<<<BNT / 2, dim3(128, 2)>>>(
            Y2, Q2, W2, b2, idxp, d2p, q, qbs, s, sbs, r2c2, f2o, 128);

        // 5) cell 3: Q3 = f2o @ Wf3, then combine
        GemmP q3d = { f2o, Wf3, Q3, 256, 128 };
        gemm_kernel<<<dim3(128, 4, 1), 128>>>(q3d, q3d, q3d);
        combine_kernel<<<BNT, dim3(256, 1)>>>(
            Y3, Q3, W3, b3, idxp, d2p, q, qbs, s, sbs, r2c3, f3o, 256);

        // 6) prediction steps: motion MLP, frame update, write output slot
        if (t >= HALF) {
            GemmP gm = { f3o, Wm, G, 64, 256 };
            gemm_kernel<<<dim3(128, 1, 1), 128>>>(gm, gm, gm);
            mlp_tail<<<BNT / 256, 256>>>(G, bm, Wl, bl, q, qbs,
                                         out + (t - HALF) * FRM, OBS);
        }
    }
}

// round 3
// speedup vs baseline: 1.1479x; 1.0431x over previous
#include <cuda_runtime.h>

typedef unsigned long long ull;

// ---------------------------------------------------------------------------
// Problem constants
// ---------------------------------------------------------------------------
#define NB    16          // batch
#define NPTS  512         // points per cloud
#define BNT   (NB*NPTS)   // 8192
#define KNN   8
#define SEQ   12
#define HALF  6

// ---------------------------------------------------------------------------
// Scratch (static device globals: no runtime allocation allowed)
// ---------------------------------------------------------------------------
__device__ __align__(16) float g_f1[2 * BNT * 64];
__device__ __align__(16) float g_f2[2 * BNT * 128];
__device__ __align__(16) float g_f3[2 * BNT * 256];
__device__ __align__(16) float g_Y1[BNT * 64];
__device__ __align__(16) float g_Y2[BNT * 128];
__device__ __align__(16) float g_Y3[BNT * 256];
__device__ __align__(16) float g_Q2[BNT * 128];
__device__ __align__(16) float g_Q3[BNT * 256];
__device__ __align__(16) float g_G [BNT * 64];
__device__ __align__(16) int   g_idx[BNT * KNN];
__device__ __align__(16) float g_d2 [BNT * KNN];

// ---------------------------------------------------------------------------
// packed f32x2 helpers (SASS FFMA2 — ptxas never emits these from C++)
// ---------------------------------------------------------------------------
__device__ __forceinline__ void ffma2(ull& d, ull a, ull b)
{
    asm("fma.rn.f32x2 %0, %1, %2, %0;" : "+l"(d) : "l"(a), "l"(b));
}
__device__ __forceinline__ float2 unpk(ull v)
{
    float2 f;
    asm("mov.b64 {%0, %1}, %2;" : "=f"(f.x), "=f"(f.y) : "l"(v));
    return f;
}

// ---------------------------------------------------------------------------
__global__ void zero_states()
{
    int stride = gridDim.x * blockDim.x;
    int i0 = blockIdx.x * blockDim.x + threadIdx.x;
    for (int i = i0; i < BNT * 64;  i += stride) g_f1[i] = 0.f;
    for (int i = i0; i < BNT * 128; i += stride) g_f2[i] = 0.f;
    for (int i = i0; i < BNT * 256; i += stride) g_f3[i] = 0.f;
}

// ---------------------------------------------------------------------------
// Double-buffered packed-f32x2 SGEMM body.
// C[M=8192, N] = A[M, K] @ B[K, N]. 64x64 tile, BK=32, 128 threads, 8m x 4n.
// ---------------------------------------------------------------------------
struct GemmP {
    const float* A;
    const float* B;
    float*       C;
    int N;
    int K;
};

__device__ __forceinline__ void gemm_body(GemmP p)
{
    int nOff = blockIdx.y * 64;
    if (nOff >= p.N) return;

    __shared__ __align__(16) float As[2][32][66];   // [buf][k][m]
    __shared__ __align__(16) float Bs[2][32][64];   // [buf][k][n]

    int tid = threadIdx.x;
    int tx = tid & 15;        // n group (4 cols)
    int ty = tid >> 4;        // m group (8 rows)

    const float* A = p.A + (blockIdx.x * 64) * p.K;
    const float* B = p.B + nOff;

    int cA  = tid & 31;   // k-col for A loads
    int rA0 = tid >> 5;   // 0..3
    int cB  = tid & 63;   // n-col for B loads
    int rB0 = tid >> 6;   // 0..1

    float ra[16], rb[16];
    #pragma unroll
    for (int i = 0; i < 16; i++) ra[i] = A[(rA0 + i*4) * p.K + cA];
    #pragma unroll
    for (int i = 0; i < 16; i++) rb[i] = B[(rB0 + i*2) * p.N + cB];
    #pragma unroll
    for (int i = 0; i < 16; i++) As[0][cA][rA0 + i*4] = ra[i];
    #pragma unroll
    for (int i = 0; i < 16; i++) Bs[0][rB0 + i*2][cB] = rb[i];
    __syncthreads();

    ull acc[4][4];
    #pragma unroll
    for (int i = 0; i < 4; i++)
        #pragma unroll
        for (int j = 0; j < 4; j++) acc[i][j] = 0ull;

    int nT = p.K >> 5;
    for (int it = 0; it < nT; it++) {
        int buf = it & 1;
        if (it + 1 < nT) {
            const float* A2 = A + (it + 1) * 32;
            const float* B2 = B + ((it + 1) * 32) * p.N;
            #pragma unroll
            for (int i = 0; i < 16; i++) ra[i] = A2[(rA0 + i*4) * p.K + cA];
            #pragma unroll
            for (int i = 0; i < 16; i++) rb[i] = B2[(rB0 + i*2) * p.N + cB];
        }

        #pragma unroll
        for (int k = 0; k < 32; k++) {
            ull a0 = *reinterpret_cast<const ull*>(&As[buf][k][ty*8 + 0]);
            ull a1 = *reinterpret_cast<const ull*>(&As[buf][k][ty*8 + 2]);
            ull a2 = *reinterpret_cast<const ull*>(&As[buf][k][ty*8 + 4]);
            ull a3 = *reinterpret_cast<const ull*>(&As[buf][k][ty*8 + 6]);
            float4 bv = *reinterpret_cast<const float4*>(&Bs[buf][k][tx*4]);
            ull b0, b1, b2, b3;
            asm("mov.b64 %0, {%1, %1};" : "=l"(b0) : "f"(bv.x));
            asm("mov.b64 %0, {%1, %1};" : "=l"(b1) : "f"(bv.y));
            asm("mov.b64 %0, {%1, %1};" : "=l"(b2) : "f"(bv.z));
            asm("mov.b64 %0, {%1, %1};" : "=l"(b3) : "f"(bv.w));
            ffma2(acc[0][0], a0, b0); ffma2(acc[0][1], a0, b1);
            ffma2(acc[0][2], a0, b2); ffma2(acc[0][3], a0, b3);
            ffma2(acc[1][0], a1, b0); ffma2(acc[1][1], a1, b1);
            ffma2(acc[1][2], a1, b2); ffma2(acc[1][3], a1, b3);
            ffma2(acc[2][0], a2, b0); ffma2(acc[2][1], a2, b1);
            ffma2(acc[2][2], a2, b2); ffma2(acc[2][3], a2, b3);
            ffma2(acc[3][0], a3, b0); ffma2(acc[3][1], a3, b1);
            ffma2(acc[3][2], a3, b2); ffma2(acc[3][3], a3, b3);
        }

        if (it + 1 < nT) {
            #pragma unroll
            for (int i = 0; i < 16; i++) As[buf^1][cA][rA0 + i*4] = ra[i];
            #pragma unroll
            for (int i = 0; i < 16; i++) Bs[buf^1][rB0 + i*2][cB] = rb[i];
            __syncthreads();
        }
    }

    float* C = p.C + (blockIdx.x * 64 + ty * 8) * p.N + nOff + tx * 4;
    #pragma unroll
    for (int pm = 0; pm < 4; pm++) {
        float2 u0 = unpk(acc[pm][0]);
        float2 u1 = unpk(acc[pm][1]);
        float2 u2 = unpk(acc[pm][2]);
        float2 u3 = unpk(acc[pm][3]);
        float4 lo = make_float4(u0.x, u1.x, u2.x, u3.x);
        float4 hi = make_float4(u0.y, u1.y, u2.y, u3.y);
        *reinterpret_cast<float4*>(C + (pm*2 + 0) * p.N) = lo;
        *reinterpret_cast<float4*>(C + (pm*2 + 1) * p.N) = hi;
    }
}

__global__ __launch_bounds__(128) void gemm_kernel(GemmP p0)
{
    gemm_body(p0);
}

// ---------------------------------------------------------------------------
// Fused step-front: z<3 -> the 3 Y GEMMs; z==3 -> top-8 neighbor search.
// (independent work, one launch)
// ---------------------------------------------------------------------------
__global__ __launch_bounds__(128) void front_kernel(
    GemmP p0, GemmP p1, GemmP p2,
    const float* __restrict__ q, int qbs,
    const float* __restrict__ s, int sbs,
    int*   __restrict__ idxOut,
    float* __restrict__ d2Out)
{
    if (blockIdx.z == 3) {
        if (blockIdx.y != 0) return;
        __shared__ float sxs[NPTS], sys[NPTS], szs[NPTS];
        int b  = blockIdx.x >> 3;
        int n0 = (blockIdx.x & 7) * 64;
        const float* sb = s + b * sbs;
        for (int i = threadIdx.x; i < NPTS; i += 128) {
            sxs[i] = sb[i*3 + 0];
            sys[i] = sb[i*3 + 1];
            szs[i] = sb[i*3 + 2];
        }
        __syncthreads();
        if (threadIdx.x >= 64) return;

        int n = n0 + threadIdx.x;
        const float* qp = q + b * qbs + n * 3;
        float qx = qp[0], qy = qp[1], qz = qp[2];

        float bd[KNN]; int bi[KNN];
        #pragma unroll
        for (int k = 0; k < KNN; k++) { bd[k] = 3.4e38f; bi[k] = 0; }

        for (int j = 0; j < NPTS; j++) {
            float dx = __fadd_rn(qx, -sxs[j]);
            float dy = __fadd_rn(qy, -sys[j]);
            float dz = __fadd_rn(qz, -szs[j]);
            float d = __fadd_rn(__fadd_rn(__fmul_rn(dx, dx), __fmul_rn(dy, dy)),
                                __fmul_rn(dz, dz));
            if (d < bd[KNN-1]) {
                bd[KNN-1] = d; bi[KNN-1] = j;
                #pragma unroll
                for (int t = KNN-1; t > 0; --t) {
                    if (bd[t] < bd[t-1]) {
                        float td = bd[t]; bd[t] = bd[t-1]; bd[t-1] = td;
                        int   ti = bi[t]; bi[t] = bi[t-1]; bi[t-1] = ti;
                    }
                }
            }
        }
        int base = (b * NPTS + n) * KNN;
        #pragma unroll
        for (int k = 0; k < KNN; k++) {
            idxOut[base + k] = bi[k];
            d2Out [base + k] = bd[k];
        }
        return;
    }
    GemmP p = (blockIdx.z == 0) ? p0 : (blockIdx.z == 1) ? p1 : p2;
    gemm_body(p);
}

// ---------------------------------------------------------------------------
// combine (f32x2): out[p, j] = bias[j] + Q[p,j] + max_k( Y[row_k,j] + disp_k.Wd[:,j] )
// Optional fused epilogue (FUSEQ): Qnext[p, 0..127] = out_row[p, 0..C-1] @ Wnext
// (Wnext cached in smem; out row available in-block).
// block = (C/2, P); each x-thread owns a column PAIR.
// ---------------------------------------------------------------------------
template<int C, int P, bool HASQ, bool FUSEQ>
__global__ __launch_bounds__((C/2)*P) void combine_kernel(
    const float* __restrict__ Y,
    const float* __restrict__ Qin,
    const float* __restrict__ W,
    const float* __restrict__ bias,
    const int*   __restrict__ idx,
    const float* __restrict__ d2,
    const float* __restrict__ qx, int qbs,
    const float* __restrict__ sx, int sbs,
    float r2,
    float* __restrict__ outF,
    const float* __restrict__ Wnext,
    float* __restrict__ Qnext)
{
    __shared__ int    sRow[P][KNN];
    __shared__ float2 sDX[P][KNN], sDY[P][KNN], sDZ[P][KNN];
    __shared__ float2 frow2[FUSEQ ? P : 1][FUSEQ ? C : 1];
    __shared__ float2 wn2[FUSEQ ? 64 : 1][FUSEQ ? 64 : 1];

    int x = threadIdx.x, y = threadIdx.y;
    int p = blockIdx.x * P + y;
    int b = p >> 9, n = p & 511;

    if (x < KNN) {
        int   raw = idx[p * KNN + x];
        int   i0  = idx[p * KNN];
        float dd  = d2 [p * KNN + x];
        int eff = (dd <= r2) ? raw : i0;
        sRow[y][x] = b * NPTS + eff;
        const float* sp = sx + b * sbs + eff * 3;
        const float* qp = qx + b * qbs + n   * 3;
        float dx = sp[0] - qp[0];
        float dy = sp[1] - qp[1];
        float dz = sp[2] - qp[2];
        sDX[y][x] = make_float2(dx, dx);
        sDY[y][x] = make_float2(dy, dy);
        sDZ[y][x] = make_float2(dz, dz);
    }
    if constexpr (FUSEQ) {
        int tid = y * (C/2) + x;
        #pragma unroll 4
        for (int i = tid; i < 64 * 64; i += (C/2) * P)
            reinterpret_cast<float2*>(wn2)[i] =
                reinterpret_cast<const float2*>(Wnext)[i];
    }
    __syncthreads();

    int j0 = 2 * x;
    ull w0 = *reinterpret_cast<const ull*>(&W[j0]);
    ull w1 = *reinterpret_cast<const ull*>(&W[C + j0]);
    ull w2 = *reinterpret_cast<const ull*>(&W[2*C + j0]);
    float2 bb = *reinterpret_cast<const float2*>(&bias[j0]);

    float mx = -3.4e38f, my = -3.4e38f;
    #pragma unroll
    for (int k = 0; k < KNN; k++) {
        int row = sRow[y][k];
        ull v = *reinterpret_cast<const ull*>(&Y[row * C + j0]);
        ffma2(v, *reinterpret_cast<const ull*>(&sDX[y][k]), w0);
        ffma2(v, *reinterpret_cast<const ull*>(&sDY[y][k]), w1);
        ffma2(v, *reinterpret_cast<const ull*>(&sDZ[y][k]), w2);
        float2 vf = unpk(v);
        mx = fmaxf(mx, vf.x);
        my = fmaxf(my, vf.y);
    }
    float2 o;
    o.x = bb.x + mx;
    o.y = bb.y + my;
    if constexpr (HASQ) {
        float2 qv = *reinterpret_cast<const float2*>(&Qin[p * C + j0]);
        o.x += qv.x; o.y += qv.y;
    }
    *reinterpret_cast<float2*>(&outF[p * C + j0]) = o;

    if constexpr (FUSEQ) {
        frow2[y][j0]     = make_float2(o.x, o.x);
        frow2[y][j0 + 1] = make_float2(o.y, o.y);
        __syncthreads();
        ull a0 = 0ull, a1 = 0ull;
        #pragma unroll 8
        for (int c = 0; c < C; c++) {
            ull f = *reinterpret_cast<const ull*>(&frow2[y][c]);
            ffma2(a0, f, *reinterpret_cast<const ull*>(&wn2[c][x]));
            ffma2(a1, f, *reinterpret_cast<const ull*>(&wn2[c][x + C/2]));
        }
        float2 q0 = unpk(a0), q1 = unpk(a1);
        *reinterpret_cast<float2*>(&Qnext[p * 128 + j0])     = q0;
        *reinterpret_cast<float2*>(&Qnext[p * 128 + C + j0]) = q1;
    }
}

// ---------------------------------------------------------------------------
// motion MLP tail: h = relu(G + bm); motion = h @ Wl + bl; dst = cur + motion
// ---------------------------------------------------------------------------
__global__ __launch_bounds__(256) void mlp_tail(
    const float* __restrict__ G,
    const float* __restrict__ bm,
    const float* __restrict__ Wl,
    const float* __restrict__ bl,
    const float* __restrict__ cur, int cbs,
    float* __restrict__ dst, int dbs)
{
    __shared__ float sWl[64 * 3];
    __shared__ float sbm[64];
    __shared__ float sbl[3];
    if (threadIdx.x < 192) sWl[threadIdx.x] = Wl[threadIdx.x];
    if (threadIdx.x < 64)  sbm[threadIdx.x] = bm[threadIdx.x];
    if (threadIdx.x < 3)   sbl[threadIdx.x] = bl[threadIdx.x];
    __syncthreads();

    int p = blockIdx.x * blockDim.x + threadIdx.x;
    float m0 = sbl[0], m1 = sbl[1], m2 = sbl[2];
    const float* g = G + p * 64;
    #pragma unroll
    for (int jj = 0; jj < 64; jj++) {
        float h = fmaxf(g[jj] + sbm[jj], 0.f);
        m0 += h * sWl[jj*3 + 0];
        m1 += h * sWl[jj*3 + 1];
        m2 += h * sWl[jj*3 + 2];
    }
    int b = p >> 9, n = p & 511;
    const float* cp = cur + b * cbs + n * 3;
    float*       dp = dst + b * dbs + n * 3;
    dp[0] = cp[0] + m0;
    dp[1] = cp[1] + m1;
    dp[2] = cp[2] + m2;
}

// ---------------------------------------------------------------------------
// host orchestration
// ---------------------------------------------------------------------------
extern "C" void kernel_launch(void* const* d_in, const int* in_sizes, int n_in,
                              void* d_out, int out_size)
{
    (void)in_sizes; (void)n_in; (void)out_size;

    const float* frames = (const float*)d_in[0];
    const float* W1 = (const float*)d_in[1];
    const float* b1 = (const float*)d_in[2];
    const float* W2 = (const float*)d_in[3];
    const float* b2 = (const float*)d_in[4];
    const float* W3 = (const float*)d_in[5];
    const float* b3 = (const float*)d_in[6];
    const float* Wm = (const float*)d_in[7];
    const float* bm = (const float*)d_in[8];
    const float* Wl = (const float*)d_in[9];
    const float* bl = (const float*)d_in[10];
    float* out = (float*)d_out;

    float *f1, *f2, *f3, *Y1, *Y2, *Y3, *Q2, *Q3, *G;
    int* idxp; float* d2p;
    { void* t;
      cudaGetSymbolAddress(&t, g_f1); f1 = (float*)t;
      cudaGetSymbolAddress(&t, g_f2); f2 = (float*)t;
      cudaGetSymbolAddress(&t, g_f3); f3 = (float*)t;
      cudaGetSymbolAddress(&t, g_Y1); Y1 = (float*)t;
      cudaGetSymbolAddress(&t, g_Y2); Y2 = (float*)t;
      cudaGetSymbolAddress(&t, g_Y3); Y3 = (float*)t;
      cudaGetSymbolAddress(&t, g_Q2); Q2 = (float*)t;
      cudaGetSymbolAddress(&t, g_Q3); Q3 = (float*)t;
      cudaGetSymbolAddress(&t, g_G);  G  = (float*)t;
      cudaGetSymbolAddress(&t, g_idx); idxp = (int*)t;
      cudaGetSymbolAddress(&t, g_d2);  d2p  = (float*)t;
    }

    const int FBS = SEQ * NPTS * 3;
    const int OBS = HALF * NPTS * 3;
    const int FRM = NPTS * 3;

    const double R0 = 4.0 + 1e-6, R1 = 8.0 + 1e-6, R2 = 12.0 + 1e-6;
    const float r2c1 = (float)(R0 * R0);
    const float r2c2 = (float)(R1 * R1);
    const float r2c3 = (float)(R2 * R2);

    // weight sub-block pointers (row-major (cin, cout))
    const float* Wn1 = W1 + 3 * 64;
    const float* Wf2 = W2 + 3 * 128;
    const float* Wn2 = W2 + (3 + 64) * 128;
    const float* Wf3 = W3 + 3 * 256;
    const float* Wn3 = W3 + (3 + 128) * 256;

    zero_states<<<256, 256>>>();

    for (int t = 0; t < SEQ; t++) {
        const float *q, *s; int qbs, sbs;
        if (t < HALF) {
            q = frames + t * FRM;                       qbs = FBS;
            s = frames + (t ? (t - 1) : 0) * FRM;       sbs = FBS;
        } else if (t == HALF) {
            q = frames + (HALF - 1) * FRM;              qbs = FBS;
            s = q;                                      sbs = FBS;
        } else if (t == HALF + 1) {
            q = out;                                    qbs = OBS;
            s = frames + (HALF - 1) * FRM;              sbs = FBS;
        } else {
            q = out + (t - HALF - 1) * FRM;             qbs = OBS;
            s = out + (t - HALF - 2) * FRM;             sbs = OBS;
        }

        int pin = t & 1, pout = 1 - pin;
        float* f1i = f1 + pin  * BNT * 64;
        float* f1o = f1 + pout * BNT * 64;
        float* f2i = f2 + pin  * BNT * 128;
        float* f2o = f2 + pout * BNT * 128;
        float* f3i = f3 + pin  * BNT * 256;
        float* f3o = f3 + pout * BNT * 256;

        // 1) fused: topk + Y GEMMs (all independent)
        GemmP y1 = { f1i, Wn1, Y1, 64, 64 };
        GemmP y2 = { f2i, Wn2, Y2, 128, 128 };
        GemmP y3 = { f3i, Wn3, Y3, 256, 256 };
        front_kernel<<<dim3(128, 4, 4), 128>>>(y1, y2, y3,
                                               q, qbs, s, sbs, idxp, d2p);

        // 2) cell 1 combine + fused Q2 = f1o @ Wf2
        combine_kernel<64, 8, false, true><<<BNT / 8, dim3(32, 8)>>>(
            Y1, nullptr, W1, b1, idxp, d2p, q, qbs, s, sbs, r2c1,
            f1o, Wf2, Q2);

        // 3) cell 2 combine
        combine_kernel<128, 4, true, false><<<BNT / 4, dim3(64, 4)>>>(
            Y2, Q2, W2, b2, idxp, d2p, q, qbs, s, sbs, r2c2,
            f2o, nullptr, nullptr);

        // 4) Q3 = f2o @ Wf3
        GemmP q3d = { f2o, Wf3, Q3, 256, 128 };
        gemm_kernel<<<dim3(128, 4, 1), 128>>>(q3d);

        // 5) cell 3 combine
        combine_kernel<256, 2, true, false><<<BNT / 2, dim3(128, 2)>>>(
            Y3, Q3, W3, b3, idxp, d2p, q, qbs, s, sbs, r2c3,
            f3o, nullptr, nullptr);

        // 6) prediction steps
        if (t >= HALF) {
            GemmP gm = { f3o, Wm, G, 64, 256 };
            gemm_kernel<<<dim3(128, 1, 1), 128>>>(gm);
            mlp_tail<<<BNT / 256, 256>>>(G, bm, Wl, bl, q, qbs,
                                         out + (t - HALF) * FRM, OBS);
        }
    }
}

// round 5
// speedup vs baseline: 1.2522x; 1.0908x over previous
#include <cuda_runtime.h>
#include <cuda_bf16.h>
#include <cstdint>

typedef unsigned long long ull;

// ---------------------------------------------------------------------------
// Problem constants
// ---------------------------------------------------------------------------
#define NB    16
#define NPTS  512
#define BNT   (NB*NPTS)   // 8192
#define KNN   8
#define SEQ   12
#define HALF  6

// ---------------------------------------------------------------------------
// Scratch (static device globals)
// ---------------------------------------------------------------------------
// state features as bf16 hi/lo ping-pong pairs
__device__ __align__(16) __nv_bfloat16 g_f1h[2 * BNT * 64],  g_f1l[2 * BNT * 64];
__device__ __align__(16) __nv_bfloat16 g_f2h[2 * BNT * 128], g_f2l[2 * BNT * 128];
__device__ __align__(16) __nv_bfloat16 g_f3h[2 * BNT * 256], g_f3l[2 * BNT * 256];
// fp32 intermediates
__device__ __align__(16) float g_Y1[BNT * 64];
__device__ __align__(16) float g_Y2[BNT * 128];
__device__ __align__(16) float g_Y3[BNT * 256];
__device__ __align__(16) float g_Q2[BNT * 128];
__device__ __align__(16) float g_Q3[BNT * 256];
__device__ __align__(16) float g_G [BNT * 64];
__device__ __align__(16) int   g_idx[BNT * KNN];
__device__ __align__(16) float g_d2 [BNT * KNN];
// weight bf16 hi/lo (plain row-major [K][N])
__device__ __align__(16) __nv_bfloat16 g_Wn1h[64*64],   g_Wn1l[64*64];
__device__ __align__(16) __nv_bfloat16 g_Wn2h[128*128], g_Wn2l[128*128];
__device__ __align__(16) __nv_bfloat16 g_Wn3h[256*256], g_Wn3l[256*256];
__device__ __align__(16) __nv_bfloat16 g_Wf3h[128*256], g_Wf3l[128*256];
__device__ __align__(16) __nv_bfloat16 g_Wmh [256*64],  g_Wml [256*64];

// ---------------------------------------------------------------------------
// packed f32x2 helpers (combine kernels)
// ---------------------------------------------------------------------------
__device__ __forceinline__ void ffma2(ull& d, ull a, ull b)
{
    asm("fma.rn.f32x2 %0, %1, %2, %0;" : "+l"(d) : "l"(a), "l"(b));
}
__device__ __forceinline__ float2 unpk(ull v)
{
    float2 f;
    asm("mov.b64 {%0, %1}, %2;" : "=f"(f.x), "=f"(f.y) : "l"(v));
    return f;
}

// ---------------------------------------------------------------------------
// HMMA primitives (sm_80+ PTX: works on plain sm_103 target)
// ---------------------------------------------------------------------------
__device__ __forceinline__ uint32_t smem_u32(const void* p)
{
    uint32_t a;
    asm("{ .reg .u64 t; cvta.to.shared.u64 t, %1; cvt.u32.u64 %0, t; }"
        : "=r"(a) : "l"(p));
    return a;
}
__device__ __forceinline__ void ldsm4(uint32_t* r, uint32_t a)
{
    asm volatile("ldmatrix.sync.aligned.m8n8.x4.shared.b16 {%0,%1,%2,%3}, [%4];"
        : "=r"(r[0]), "=r"(r[1]), "=r"(r[2]), "=r"(r[3]) : "r"(a));
}
__device__ __forceinline__ void ldsm4t(uint32_t* r, uint32_t a)
{
    asm volatile("ldmatrix.sync.aligned.m8n8.x4.trans.shared.b16 {%0,%1,%2,%3}, [%4];"
        : "=r"(r[0]), "=r"(r[1]), "=r"(r[2]), "=r"(r[3]) : "r"(a));
}
__device__ __forceinline__ void mma16816(float* d, const uint32_t* a,
                                         uint32_t b0, uint32_t b1)
{
    asm volatile(
        "mma.sync.aligned.m16n8k16.row.col.f32.bf16.bf16.f32 "
        "{%0,%1,%2,%3}, {%4,%5,%6,%7}, {%8,%9}, {%0,%1,%2,%3};"
        : "+f"(d[0]), "+f"(d[1]), "+f"(d[2]), "+f"(d[3])
        : "r"(a[0]), "r"(a[1]), "r"(a[2]), "r"(a[3]), "r"(b0), "r"(b1));
}

// ---------------------------------------------------------------------------
__global__ void zero_states()
{
    int stride = gridDim.x * blockDim.x;
    int i0 = blockIdx.x * blockDim.x + threadIdx.x;
    uint32_t* a;
    a = reinterpret_cast<uint32_t*>(g_f1h);
    for (int i = i0; i < BNT * 64;  i += stride) a[i] = 0u;
    a = reinterpret_cast<uint32_t*>(g_f1l);
    for (int i = i0; i < BNT * 64;  i += stride) a[i] = 0u;
    a = reinterpret_cast<uint32_t*>(g_f2h);
    for (int i = i0; i < BNT * 128; i += stride) a[i] = 0u;
    a = reinterpret_cast<uint32_t*>(g_f2l);
    for (int i = i0; i < BNT * 128; i += stride) a[i] = 0u;
    a = reinterpret_cast<uint32_t*>(g_f3h);
    for (int i = i0; i < BNT * 256; i += stride) a[i] = 0u;
    a = reinterpret_cast<uint32_t*>(g_f3l);
    for (int i = i0; i < BNT * 256; i += stride) a[i] = 0u;
}

// ---------------------------------------------------------------------------
// weight -> bf16 hi/lo conversion (plain row-major)
// ---------------------------------------------------------------------------
__global__ void wconv_kernel(const float* __restrict__ W,
                             __nv_bfloat16* __restrict__ hi,
                             __nv_bfloat16* __restrict__ lo,
                             int total)
{
    int idx = blockIdx.x * 256 + threadIdx.x;
    if (idx >= total) return;
    float x = W[idx];
    __nv_bfloat16 h = __float2bfloat16_rn(x);
    __nv_bfloat16 l = __float2bfloat16_rn(x - __bfloat162float(h));
    hi[idx] = h;
    lo[idx] = l;
}

// ---------------------------------------------------------------------------
// Split-bf16 HMMA GEMM body: C[8192, N] = (Ah+Al)[8192, K] @ (Bh+Bl)[K, N]
// block = 4 warps, 64x64 tile (warp = 16m x 64n), BK = 32.
// smem layout (19456 B): Ah[64][40] | Al[64][40] | Bh[32][72] | Bl[32][72]
// ---------------------------------------------------------------------------
struct HmmaP {
    const __nv_bfloat16 *Ah, *Al, *Bh, *Bl;
    float* C;
    int N, K;
};

#define SMEM_BYTES 19456

__device__ __forceinline__ void hmma_body(const HmmaP& p, char* sm)
{
    int nStrip = blockIdx.y * 64;
    if (nStrip >= p.N) return;

    __nv_bfloat16 (*sAh)[40] = reinterpret_cast<__nv_bfloat16(*)[40]>(sm);
    __nv_bfloat16 (*sAl)[40] = reinterpret_cast<__nv_bfloat16(*)[40]>(sm + 5120);
    __nv_bfloat16 (*sBh)[72] = reinterpret_cast<__nv_bfloat16(*)[72]>(sm + 10240);
    __nv_bfloat16 (*sBl)[72] = reinterpret_cast<__nv_bfloat16(*)[72]>(sm + 14848);

    int tid = threadIdx.x, warp = tid >> 5, lane = tid & 31;
    int m0 = blockIdx.x * 64;

    float acc[8][4];
    #pragma unroll
    for (int i = 0; i < 8; i++)
        #pragma unroll
        for (int j = 0; j < 4; j++) acc[i][j] = 0.f;

    int aRow = warp * 16 + (lane & 15);
    int hi8  = (lane >> 4) * 8;
    int bRow = lane & 15;

    for (int k0 = 0; k0 < p.K; k0 += 32) {
        // ---- stage A (64x32) hi+lo ----
        #pragma unroll
        for (int i = 0; i < 2; i++) {
            int id = tid + i * 128;
            int r = id >> 2, c = (id & 3) * 8;
            const __nv_bfloat16* gh = p.Ah + (size_t)(m0 + r) * p.K + k0 + c;
            const __nv_bfloat16* gl = p.Al + (size_t)(m0 + r) * p.K + k0 + c;
            *reinterpret_cast<uint4*>(&sAh[r][c]) = *reinterpret_cast<const uint4*>(gh);
            *reinterpret_cast<uint4*>(&sAl[r][c]) = *reinterpret_cast<const uint4*>(gl);
        }
        // ---- stage B (32x64) hi+lo ----
        #pragma unroll
        for (int i = 0; i < 2; i++) {
            int id = tid + i * 128;
            int r = id >> 3, c = (id & 7) * 8;
            const __nv_bfloat16* gh = p.Bh + (size_t)(k0 + r) * p.N + nStrip + c;
            const __nv_bfloat16* gl = p.Bl + (size_t)(k0 + r) * p.N + nStrip + c;
            *reinterpret_cast<uint4*>(&sBh[r][c]) = *reinterpret_cast<const uint4*>(gh);
            *reinterpret_cast<uint4*>(&sBl[r][c]) = *reinterpret_cast<const uint4*>(gl);
        }
        __syncthreads();

        #pragma unroll
        for (int kk = 0; kk < 32; kk += 16) {
            uint32_t ah[4], al[4];
            ldsm4(ah, smem_u32(&sAh[aRow][kk + hi8]));
            ldsm4(al, smem_u32(&sAl[aRow][kk + hi8]));
            #pragma unroll
            for (int np = 0; np < 4; np++) {
                uint32_t bh[4], bl[4];
                ldsm4t(bh, smem_u32(&sBh[kk + bRow][np * 16 + hi8]));
                ldsm4t(bl, smem_u32(&sBl[kk + bRow][np * 16 + hi8]));
                mma16816(acc[np*2],     ah, bh[0], bh[1]);
                mma16816(acc[np*2],     ah, bl[0], bl[1]);
                mma16816(acc[np*2],     al, bh[0], bh[1]);
                mma16816(acc[np*2 + 1], ah, bh[2], bh[3]);
                mma16816(acc[np*2 + 1], ah, bl[2], bl[3]);
                mma16816(acc[np*2 + 1], al, bh[2], bh[3]);
            }
        }
        __syncthreads();
    }

    // ---- epilogue: d-frag m16n8 layout ----
    int g = lane >> 2, tg = lane & 3;
    float* Crow = p.C + (size_t)(m0 + warp * 16 + g) * p.N + nStrip + tg * 2;
    #pragma unroll
    for (int ng = 0; ng < 8; ng++) {
        *reinterpret_cast<float2*>(Crow + ng * 8) =
            make_float2(acc[ng][0], acc[ng][1]);
        *reinterpret_cast<float2*>(Crow + (size_t)8 * p.N + ng * 8) =
            make_float2(acc[ng][2], acc[ng][3]);
    }
}

__global__ __launch_bounds__(128) void hmma_kernel(HmmaP p0)
{
    __shared__ __align__(16) char sm[SMEM_BYTES];
    hmma_body(p0, sm);
}

// ---------------------------------------------------------------------------
// Fused step-front: z<3 -> Y GEMMs (HMMA), z==3 -> top-8 neighbor search
// ---------------------------------------------------------------------------
__global__ __launch_bounds__(128) void front_kernel(
    HmmaP p0, HmmaP p1, HmmaP p2,
    const float* __restrict__ q, int qbs,
    const float* __restrict__ s, int sbs,
    int*   __restrict__ idxOut,
    float* __restrict__ d2Out)
{
    __shared__ __align__(16) char sm[SMEM_BYTES];
    if (blockIdx.z == 3) {
        if (blockIdx.y != 0) return;
        float* sxs = reinterpret_cast<float*>(sm);
        float* sys = sxs + NPTS;
        float* szs = sys + NPTS;
        int b  = blockIdx.x >> 3;
        int n0 = (blockIdx.x & 7) * 64;
        const float* sb = s + b * sbs;
        for (int i = threadIdx.x; i < NPTS; i += 128) {
            sxs[i] = sb[i*3 + 0];
            sys[i] = sb[i*3 + 1];
            szs[i] = sb[i*3 + 2];
        }
        __syncthreads();
        if (threadIdx.x >= 64) return;

        int n = n0 + threadIdx.x;
        const float* qp = q + b * qbs + n * 3;
        float qx = qp[0], qy = qp[1], qz = qp[2];

        float bd[KNN]; int bi[KNN];
        #pragma unroll
        for (int k = 0; k < KNN; k++) { bd[k] = 3.4e38f; bi[k] = 0; }

        for (int j = 0; j < NPTS; j++) {
            float dx = __fadd_rn(qx, -sxs[j]);
            float dy = __fadd_rn(qy, -sys[j]);
            float dz = __fadd_rn(qz, -szs[j]);
            float d = __fadd_rn(__fadd_rn(__fmul_rn(dx, dx), __fmul_rn(dy, dy)),
                                __fmul_rn(dz, dz));
            if (d < bd[KNN-1]) {
                bd[KNN-1] = d; bi[KNN-1] = j;
                #pragma unroll
                for (int t = KNN-1; t > 0; --t) {
                    if (bd[t] < bd[t-1]) {
                        float td = bd[t]; bd[t] = bd[t-1]; bd[t-1] = td;
                        int   ti = bi[t]; bi[t] = bi[t-1]; bi[t-1] = ti;
                    }
                }
            }
        }
        int base = (b * NPTS + n) * KNN;
        #pragma unroll
        for (int k = 0; k < KNN; k++) {
            idxOut[base + k] = bi[k];
            d2Out [base + k] = bd[k];
        }
        return;
    }
    const HmmaP& p = (blockIdx.z == 0) ? p0 : (blockIdx.z == 1) ? p1 : p2;
    hmma_body(p, sm);
}

// ---------------------------------------------------------------------------
// combine (f32x2): o[p,j] = bias[j] + Q[p,j] + max_k( Y[row_k,j] + disp_k.Wd[:,j] )
// Outputs bf16 hi/lo state arrays. FUSEQ: Qnext = o_row @ Wnext (fp32 exact).
// ---------------------------------------------------------------------------
template<int C, int P, bool HASQ, bool FUSEQ>
__global__ __launch_bounds__((C/2)*P) void combine_kernel(
    const float* __restrict__ Y,
    const float* __restrict__ Qin,
    const float* __restrict__ W,
    const float* __restrict__ bias,
    const int*   __restrict__ idx,
    const float* __restrict__ d2,
    const float* __restrict__ qx, int qbs,
    const float* __restrict__ sx, int sbs,
    float r2,
    __nv_bfloat16* __restrict__ outH,
    __nv_bfloat16* __restrict__ outL,
    const float* __restrict__ Wnext,
    float* __restrict__ Qnext)
{
    __shared__ int    sRow[P][KNN];
    __shared__ float2 sDX[P][KNN], sDY[P][KNN], sDZ[P][KNN];
    __shared__ float2 frow2[FUSEQ ? P : 1][FUSEQ ? C : 1];
    __shared__ float2 wn2[FUSEQ ? 64 : 1][FUSEQ ? 64 : 1];

    int x = threadIdx.x, y = threadIdx.y;
    int p = blockIdx.x * P + y;
    int b = p >> 9, n = p & 511;

    if (x < KNN) {
        int   raw = idx[p * KNN + x];
        int   i0  = idx[p * KNN];
        float dd  = d2 [p * KNN + x];
        int eff = (dd <= r2) ? raw : i0;
        sRow[y][x] = b * NPTS + eff;
        const float* sp = sx + b * sbs + eff * 3;
        const float* qp = qx + b * qbs + n   * 3;
        float dx = sp[0] - qp[0];
        float dy = sp[1] - qp[1];
        float dz = sp[2] - qp[2];
        sDX[y][x] = make_float2(dx, dx);
        sDY[y][x] = make_float2(dy, dy);
        sDZ[y][x] = make_float2(dz, dz);
    }
    if constexpr (FUSEQ) {
        int tid = y * (C/2) + x;
        #pragma unroll 4
        for (int i = tid; i < 64 * 64; i += (C/2) * P)
            reinterpret_cast<float2*>(wn2)[i] =
                reinterpret_cast<const float2*>(Wnext)[i];
    }
    __syncthreads();

    int j0 = 2 * x;
    ull w0 = *reinterpret_cast<const ull*>(&W[j0]);
    ull w1 = *reinterpret_cast<const ull*>(&W[C + j0]);
    ull w2 = *reinterpret_cast<const ull*>(&W[2*C + j0]);
    float2 bb = *reinterpret_cast<const float2*>(&bias[j0]);

    float mx = -3.4e38f, my = -3.4e38f;
    #pragma unroll
    for (int k = 0; k < KNN; k++) {
        int row = sRow[y][k];
        ull v = *reinterpret_cast<const ull*>(&Y[row * C + j0]);
        ffma2(v, *reinterpret_cast<const ull*>(&sDX[y][k]), w0);
        ffma2(v, *reinterpret_cast<const ull*>(&sDY[y][k]), w1);
        ffma2(v, *reinterpret_cast<const ull*>(&sDZ[y][k]), w2);
        float2 vf = unpk(v);
        mx = fmaxf(mx, vf.x);
        my = fmaxf(my, vf.y);
    }
    float2 o;
    o.x = bb.x + mx;
    o.y = bb.y + my;
    if constexpr (HASQ) {
        float2 qv = *reinterpret_cast<const float2*>(&Qin[p * C + j0]);
        o.x += qv.x; o.y += qv.y;
    }
    // bf16 hi/lo split of the fp32 state value
    {
        __nv_bfloat16 hx = __float2bfloat16_rn(o.x);
        __nv_bfloat16 hy = __float2bfloat16_rn(o.y);
        __nv_bfloat16 lx = __float2bfloat16_rn(o.x - __bfloat162float(hx));
        __nv_bfloat16 ly = __float2bfloat16_rn(o.y - __bfloat162float(hy));
        uint32_t ph = (uint32_t)*reinterpret_cast<uint16_t*>(&hx)
                    | ((uint32_t)*reinterpret_cast<uint16_t*>(&hy) << 16);
        uint32_t pl = (uint32_t)*reinterpret_cast<uint16_t*>(&lx)
                    | ((uint32_t)*reinterpret_cast<uint16_t*>(&ly) << 16);
        *reinterpret_cast<uint32_t*>(&outH[p * C + j0]) = ph;
        *reinterpret_cast<uint32_t*>(&outL[p * C + j0]) = pl;
    }

    if constexpr (FUSEQ) {
        frow2[y][j0]     = make_float2(o.x, o.x);
        frow2[y][j0 + 1] = make_float2(o.y, o.y);
        __syncthreads();
        ull a0 = 0ull, a1 = 0ull;
        #pragma unroll 8
        for (int c = 0; c < C; c++) {
            ull f = *reinterpret_cast<const ull*>(&frow2[y][c]);
            ffma2(a0, f, *reinterpret_cast<const ull*>(&wn2[c][x]));
            ffma2(a1, f, *reinterpret_cast<const ull*>(&wn2[c][x + C/2]));
        }
        float2 q0 = unpk(a0), q1 = unpk(a1);
        *reinterpret_cast<float2*>(&Qnext[p * 128 + j0])     = q0;
        *reinterpret_cast<float2*>(&Qnext[p * 128 + C + j0]) = q1;
    }
}

// ---------------------------------------------------------------------------
// motion MLP tail
// ---------------------------------------------------------------------------
__global__ __launch_bounds__(256) void mlp_tail(
    const float* __restrict__ G,
    const float* __restrict__ bm,
    const float* __restrict__ Wl,
    const float* __restrict__ bl,
    const float* __restrict__ cur, int cbs,
    float* __restrict__ dst, int dbs)
{
    __shared__ float sWl[64 * 3];
    __shared__ float sbm[64];
    __shared__ float sbl[3];
    if (threadIdx.x < 192) sWl[threadIdx.x] = Wl[threadIdx.x];
    if (threadIdx.x < 64)  sbm[threadIdx.x] = bm[threadIdx.x];
    if (threadIdx.x < 3)   sbl[threadIdx.x] = bl[threadIdx.x];
    __syncthreads();

    int p = blockIdx.x * blockDim.x + threadIdx.x;
    float m0 = sbl[0], m1 = sbl[1], m2 = sbl[2];
    const float* g = G + p * 64;
    #pragma unroll
    for (int jj = 0; jj < 64; jj++) {
        float h = fmaxf(g[jj] + sbm[jj], 0.f);
        m0 += h * sWl[jj*3 + 0];
        m1 += h * sWl[jj*3 + 1];
        m2 += h * sWl[jj*3 + 2];
    }
    int b = p >> 9, n = p & 511;
    const float* cp = cur + b * cbs + n * 3;
    float*       dp = dst + b * dbs + n * 3;
    dp[0] = cp[0] + m0;
    dp[1] = cp[1] + m1;
    dp[2] = cp[2] + m2;
}

// ---------------------------------------------------------------------------
// host orchestration
// ---------------------------------------------------------------------------
extern "C" void kernel_launch(void* const* d_in, const int* in_sizes, int n_in,
                              void* d_out, int out_size)
{
    (void)in_sizes; (void)n_in; (void)out_size;

    const float* frames = (const float*)d_in[0];
    const float* W1 = (const float*)d_in[1];
    const float* b1 = (const float*)d_in[2];
    const float* W2 = (const float*)d_in[3];
    const float* b2 = (const float*)d_in[4];
    const float* W3 = (const float*)d_in[5];
    const float* b3 = (const float*)d_in[6];
    const float* Wm = (const float*)d_in[7];
    const float* bm = (const float*)d_in[8];
    const float* Wl = (const float*)d_in[9];
    const float* bl = (const float*)d_in[10];
    float* out = (float*)d_out;

    __nv_bfloat16 *f1h, *f1l, *f2h, *f2l, *f3h, *f3l;
    float *Y1, *Y2, *Y3, *Q2, *Q3, *G;
    int* idxp; float* d2p;
    __nv_bfloat16 *wn1h, *wn1l, *wn2h, *wn2l, *wn3h, *wn3l, *wf3h, *wf3l, *wmh, *wml;
    { void* t;
      cudaGetSymbolAddress(&t, g_f1h); f1h = (__nv_bfloat16*)t;
      cudaGetSymbolAddress(&t, g_f1l); f1l = (__nv_bfloat16*)t;
      cudaGetSymbolAddress(&t, g_f2h); f2h = (__nv_bfloat16*)t;
      cudaGetSymbolAddress(&t, g_f2l); f2l = (__nv_bfloat16*)t;
      cudaGetSymbolAddress(&t, g_f3h); f3h = (__nv_bfloat16*)t;
      cudaGetSymbolAddress(&t, g_f3l); f3l = (__nv_bfloat16*)t;
      cudaGetSymbolAddress(&t, g_Y1); Y1 = (float*)t;
      cudaGetSymbolAddress(&t, g_Y2); Y2 = (float*)t;
      cudaGetSymbolAddress(&t, g_Y3); Y3 = (float*)t;
      cudaGetSymbolAddress(&t, g_Q2); Q2 = (float*)t;
      cudaGetSymbolAddress(&t, g_Q3); Q3 = (float*)t;
      cudaGetSymbolAddress(&t, g_G);  G  = (float*)t;
      cudaGetSymbolAddress(&t, g_idx); idxp = (int*)t;
      cudaGetSymbolAddress(&t, g_d2);  d2p  = (float*)t;
      cudaGetSymbolAddress(&t, g_Wn1h); wn1h = (__nv_bfloat16*)t;
      cudaGetSymbolAddress(&t, g_Wn1l); wn1l = (__nv_bfloat16*)t;
      cudaGetSymbolAddress(&t, g_Wn2h); wn2h = (__nv_bfloat16*)t;
      cudaGetSymbolAddress(&t, g_Wn2l); wn2l = (__nv_bfloat16*)t;
      cudaGetSymbolAddress(&t, g_Wn3h); wn3h = (__nv_bfloat16*)t;
      cudaGetSymbolAddress(&t, g_Wn3l); wn3l = (__nv_bfloat16*)t;
      cudaGetSymbolAddress(&t, g_Wf3h); wf3h = (__nv_bfloat16*)t;
      cudaGetSymbolAddress(&t, g_Wf3l); wf3l = (__nv_bfloat16*)t;
      cudaGetSymbolAddress(&t, g_Wmh);  wmh  = (__nv_bfloat16*)t;
      cudaGetSymbolAddress(&t, g_Wml);  wml  = (__nv_bfloat16*)t;
    }

    const int FBS = SEQ * NPTS * 3;
    const int OBS = HALF * NPTS * 3;
    const int FRM = NPTS * 3;

    const double R0 = 4.0 + 1e-6, R1 = 8.0 + 1e-6, R2 = 12.0 + 1e-6;
    const float r2c1 = (float)(R0 * R0);
    const float r2c2 = (float)(R1 * R1);
    const float r2c3 = (float)(R2 * R2);

    // weight sub-block pointers (row-major (cin, cout))
    const float* Wn1 = W1 + 3 * 64;
    const float* Wf2 = W2 + 3 * 128;
    const float* Wn2 = W2 + (3 + 64) * 128;
    const float* Wf3 = W3 + 3 * 256;
    const float* Wn3 = W3 + (3 + 128) * 256;

    zero_states<<<256, 256>>>();
    wconv_kernel<<<(64*64   + 255)/256, 256>>>(Wn1, wn1h, wn1l, 64*64);
    wconv_kernel<<<(128*128 + 255)/256, 256>>>(Wn2, wn2h, wn2l, 128*128);
    wconv_kernel<<<(256*256 + 255)/256, 256>>>(Wn3, wn3h, wn3l, 256*256);
    wconv_kernel<<<(128*256 + 255)/256, 256>>>(Wf3, wf3h, wf3l, 128*256);
    wconv_kernel<<<(256*64  + 255)/256, 256>>>(Wm,  wmh,  wml,  256*64);

    for (int t = 0; t < SEQ; t++) {
        const float *q, *s; int qbs, sbs;
        if (t < HALF) {
            q = frames + t * FRM;                       qbs = FBS;
            s = frames + (t ? (t - 1) : 0) * FRM;       sbs = FBS;
        } else if (t == HALF) {
            q = frames + (HALF - 1) * FRM;              qbs = FBS;
            s = q;                                      sbs = FBS;
        } else if (t == HALF + 1) {
            q = out;                                    qbs = OBS;
            s = frames + (HALF - 1) * FRM;              sbs = FBS;
        } else {
            q = out + (t - HALF - 1) * FRM;             qbs = OBS;
            s = out + (t - HALF - 2) * FRM;             sbs = OBS;
        }

        int pin = t & 1, pout = 1 - pin;
        __nv_bfloat16* f1ih = f1h + pin  * BNT * 64;
        __nv_bfloat16* f1il = f1l + pin  * BNT * 64;
        __nv_bfloat16* f1oh = f1h + pout * BNT * 64;
        __nv_bfloat16* f1ol = f1l + pout * BNT * 64;
        __nv_bfloat16* f2ih = f2h + pin  * BNT * 128;
        __nv_bfloat16* f2il = f2l + pin  * BNT * 128;
        __nv_bfloat16* f2oh = f2h + pout * BNT * 128;
        __nv_bfloat16* f2ol = f2l + pout * BNT * 128;
        __nv_bfloat16* f3ih = f3h + pin  * BNT * 256;
        __nv_bfloat16* f3il = f3l + pin  * BNT * 256;
        __nv_bfloat16* f3oh = f3h + pout * BNT * 256;
        __nv_bfloat16* f3ol = f3l + pout * BNT * 256;

        // 1) fused: topk + Y GEMMs (HMMA)
        HmmaP y1 = { f1ih, f1il, wn1h, wn1l, Y1, 64, 64 };
        HmmaP y2 = { f2ih, f2il, wn2h, wn2l, Y2, 128, 128 };
        HmmaP y3 = { f3ih, f3il, wn3h, wn3l, Y3, 256, 256 };
        front_kernel<<<dim3(128, 4, 4), 128>>>(
            y1, y2, y3, q, qbs, s, sbs, idxp, d2p);

        // 2) cell 1 combine + fused Q2 = f1o @ Wf2 (fp32 exact)
        combine_kernel<64, 8, false, true><<<BNT / 8, dim3(32, 8)>>>(
            Y1, nullptr, W1, b1, idxp, d2p, q, qbs, s, sbs, r2c1,
            f1oh, f1ol, Wf2, Q2);

        // 3) cell 2 combine
        combine_kernel<128, 4, true, false><<<BNT / 4, dim3(64, 4)>>>(
            Y2, Q2, W2, b2, idxp, d2p, q, qbs, s, sbs, r2c2,
            f2oh, f2ol, nullptr, nullptr);

        // 4) Q3 = f2o @ Wf3 (HMMA)
        HmmaP q3d = { f2oh, f2ol, wf3h, wf3l, Q3, 256, 128 };
        hmma_kernel<<<dim3(128, 4), 128>>>(q3d);

        // 5) cell 3 combine
        combine_kernel<256, 2, true, false><<<BNT / 2, dim3(128, 2)>>>(
            Y3, Q3, W3, b3, idxp, d2p, q, qbs, s, sbs, r2c3,
            f3oh, f3ol, nullptr, nullptr);

        // 6) prediction steps
        if (t >= HALF) {
            HmmaP gm = { f3oh, f3ol, wmh, wml, G, 64, 256 };
            hmma_kernel<<<dim3(128, 1), 128>>>(gm);
            mlp_tail<<<BNT / 256, 256>>>(G, bm, Wl, bl, q, qbs,
                                         out + (t - HALF) * FRM, OBS);
        }
    }
}

// round 6
// speedup vs baseline: 1.5213x; 1.2149x over previous
#include <cuda_runtime.h>
#include <cuda_bf16.h>
#include <cstdint>

typedef unsigned long long ull;

#define NB    16
#define NPTS  512
#define BNT   (NB*NPTS)   // 8192
#define KNN   8
#define SEQ   12
#define HALF  6

// ---------------------------------------------------------------------------
// Scratch (static device globals)
// ---------------------------------------------------------------------------
__device__ __align__(16) __nv_bfloat16 g_f1h[2 * BNT * 64],  g_f1l[2 * BNT * 64];
__device__ __align__(16) __nv_bfloat16 g_f2h[2 * BNT * 128], g_f2l[2 * BNT * 128];
__device__ __align__(16) __nv_bfloat16 g_f3h[2 * BNT * 256], g_f3l[2 * BNT * 256];
__device__ __align__(16) float g_Y1[BNT * 64];
__device__ __align__(16) float g_Y2[BNT * 128];
__device__ __align__(16) float g_Y3[BNT * 256];
__device__ __align__(16) float g_Q2[BNT * 128];
__device__ __align__(16) float g_Q3[BNT * 256];
__device__ __align__(16) int   g_idx[BNT * KNN];
__device__ __align__(16) float g_d2 [BNT * KNN];
__device__ __align__(16) __nv_bfloat16 g_Wn1h[64*64],   g_Wn1l[64*64];
__device__ __align__(16) __nv_bfloat16 g_Wn2h[128*128], g_Wn2l[128*128];
__device__ __align__(16) __nv_bfloat16 g_Wn3h[256*256], g_Wn3l[256*256];
__device__ __align__(16) __nv_bfloat16 g_Wf3h[128*256], g_Wf3l[128*256];
__device__ __align__(16) __nv_bfloat16 g_Wmh [256*64],  g_Wml [256*64];

// ---------------------------------------------------------------------------
// packed f32x2 helpers
// ---------------------------------------------------------------------------
__device__ __forceinline__ void ffma2(ull& d, ull a, ull b)
{
    asm("fma.rn.f32x2 %0, %1, %2, %0;" : "+l"(d) : "l"(a), "l"(b));
}
__device__ __forceinline__ float2 unpk(ull v)
{
    float2 f;
    asm("mov.b64 {%0, %1}, %2;" : "=f"(f.x), "=f"(f.y) : "l"(v));
    return f;
}

// ---------------------------------------------------------------------------
// HMMA primitives (sm_80+ PTX: works on plain sm_103 target)
// ---------------------------------------------------------------------------
__device__ __forceinline__ uint32_t smem_u32(const void* p)
{
    uint32_t a;
    asm("{ .reg .u64 t; cvta.to.shared.u64 t, %1; cvt.u32.u64 %0, t; }"
        : "=r"(a) : "l"(p));
    return a;
}
__device__ __forceinline__ void ldsm4(uint32_t* r, uint32_t a)
{
    asm volatile("ldmatrix.sync.aligned.m8n8.x4.shared.b16 {%0,%1,%2,%3}, [%4];"
        : "=r"(r[0]), "=r"(r[1]), "=r"(r[2]), "=r"(r[3]) : "r"(a));
}
__device__ __forceinline__ void ldsm4t(uint32_t* r, uint32_t a)
{
    asm volatile("ldmatrix.sync.aligned.m8n8.x4.trans.shared.b16 {%0,%1,%2,%3}, [%4];"
        : "=r"(r[0]), "=r"(r[1]), "=r"(r[2]), "=r"(r[3]) : "r"(a));
}
__device__ __forceinline__ void mma16816(float* d, const uint32_t* a,
                                         uint32_t b0, uint32_t b1)
{
    asm volatile(
        "mma.sync.aligned.m16n8k16.row.col.f32.bf16.bf16.f32 "
        "{%0,%1,%2,%3}, {%4,%5,%6,%7}, {%8,%9}, {%0,%1,%2,%3};"
        : "+f"(d[0]), "+f"(d[1]), "+f"(d[2]), "+f"(d[3])
        : "r"(a[0]), "r"(a[1]), "r"(a[2]), "r"(a[3]), "r"(b0), "r"(b1));
}

// ---------------------------------------------------------------------------
// single init kernel: zero states + all 5 weight hi/lo conversions
// ---------------------------------------------------------------------------
__device__ __forceinline__ void wsplit(const float* W, __nv_bfloat16* hi,
                                       __nv_bfloat16* lo, int total,
                                       int i0, int stride)
{
    for (int i = i0; i < total; i += stride) {
        float x = W[i];
        __nv_bfloat16 h = __float2bfloat16_rn(x);
        __nv_bfloat16 l = __float2bfloat16_rn(x - __bfloat162float(h));
        hi[i] = h;
        lo[i] = l;
    }
}

__global__ void init_kernel(const float* __restrict__ Wn1,
                            const float* __restrict__ Wn2,
                            const float* __restrict__ Wn3,
                            const float* __restrict__ Wf3,
                            const float* __restrict__ Wm)
{
    int stride = gridDim.x * blockDim.x;
    int i0 = blockIdx.x * blockDim.x + threadIdx.x;
    uint32_t* a;
    a = reinterpret_cast<uint32_t*>(g_f1h);
    for (int i = i0; i < BNT * 64;  i += stride) a[i] = 0u;
    a = reinterpret_cast<uint32_t*>(g_f1l);
    for (int i = i0; i < BNT * 64;  i += stride) a[i] = 0u;
    a = reinterpret_cast<uint32_t*>(g_f2h);
    for (int i = i0; i < BNT * 128; i += stride) a[i] = 0u;
    a = reinterpret_cast<uint32_t*>(g_f2l);
    for (int i = i0; i < BNT * 128; i += stride) a[i] = 0u;
    a = reinterpret_cast<uint32_t*>(g_f3h);
    for (int i = i0; i < BNT * 256; i += stride) a[i] = 0u;
    a = reinterpret_cast<uint32_t*>(g_f3l);
    for (int i = i0; i < BNT * 256; i += stride) a[i] = 0u;

    wsplit(Wn1, g_Wn1h, g_Wn1l, 64*64,   i0, stride);
    wsplit(Wn2, g_Wn2h, g_Wn2l, 128*128, i0, stride);
    wsplit(Wn3, g_Wn3h, g_Wn3l, 256*256, i0, stride);
    wsplit(Wf3, g_Wf3h, g_Wf3l, 128*256, i0, stride);
    wsplit(Wm,  g_Wmh,  g_Wml,  256*64,  i0, stride);
}

// ---------------------------------------------------------------------------
// Split-bf16 HMMA GEMM body (validated round 5)
// ---------------------------------------------------------------------------
struct HmmaP {
    const __nv_bfloat16 *Ah, *Al, *Bh, *Bl;
    float* C;
    int N, K;
};

#define SMEM_BYTES 19456

template<bool MLP>
__device__ __forceinline__ void hmma_body(const HmmaP& p, char* sm,
    const float* bm, const float* Wl, const float* bl,
    const float* cur, int cbs, float* dst, int dbs)
{
    int nStrip = blockIdx.y * 64;
    if (nStrip >= p.N) return;

    __nv_bfloat16 (*sAh)[40] = reinterpret_cast<__nv_bfloat16(*)[40]>(sm);
    __nv_bfloat16 (*sAl)[40] = reinterpret_cast<__nv_bfloat16(*)[40]>(sm + 5120);
    __nv_bfloat16 (*sBh)[72] = reinterpret_cast<__nv_bfloat16(*)[72]>(sm + 10240);
    __nv_bfloat16 (*sBl)[72] = reinterpret_cast<__nv_bfloat16(*)[72]>(sm + 14848);

    int tid = threadIdx.x, warp = tid >> 5, lane = tid & 31;
    int m0 = blockIdx.x * 64;

    float acc[8][4];
    #pragma unroll
    for (int i = 0; i < 8; i++)
        #pragma unroll
        for (int j = 0; j < 4; j++) acc[i][j] = 0.f;

    int aRow = warp * 16 + (lane & 15);
    int hi8  = (lane >> 4) * 8;
    int bRow = lane & 15;

    for (int k0 = 0; k0 < p.K; k0 += 32) {
        #pragma unroll
        for (int i = 0; i < 2; i++) {
            int id = tid + i * 128;
            int r = id >> 2, c = (id & 3) * 8;
            const __nv_bfloat16* gh = p.Ah + (size_t)(m0 + r) * p.K + k0 + c;
            const __nv_bfloat16* gl = p.Al + (size_t)(m0 + r) * p.K + k0 + c;
            *reinterpret_cast<uint4*>(&sAh[r][c]) = *reinterpret_cast<const uint4*>(gh);
            *reinterpret_cast<uint4*>(&sAl[r][c]) = *reinterpret_cast<const uint4*>(gl);
        }
        #pragma unroll
        for (int i = 0; i < 2; i++) {
            int id = tid + i * 128;
            int r = id >> 3, c = (id & 7) * 8;
            const __nv_bfloat16* gh = p.Bh + (size_t)(k0 + r) * p.N + nStrip + c;
            const __nv_bfloat16* gl = p.Bl + (size_t)(k0 + r) * p.N + nStrip + c;
            *reinterpret_cast<uint4*>(&sBh[r][c]) = *reinterpret_cast<const uint4*>(gh);
            *reinterpret_cast<uint4*>(&sBl[r][c]) = *reinterpret_cast<const uint4*>(gl);
        }
        __syncthreads();

        #pragma unroll
        for (int kk = 0; kk < 32; kk += 16) {
            uint32_t ah[4], al[4];
            ldsm4(ah, smem_u32(&sAh[aRow][kk + hi8]));
            ldsm4(al, smem_u32(&sAl[aRow][kk + hi8]));
            #pragma unroll
            for (int np = 0; np < 4; np++) {
                uint32_t bh[4], bl2[4];
                ldsm4t(bh,  smem_u32(&sBh[kk + bRow][np * 16 + hi8]));
                ldsm4t(bl2, smem_u32(&sBl[kk + bRow][np * 16 + hi8]));
                mma16816(acc[np*2],     ah, bh[0], bh[1]);
                mma16816(acc[np*2],     ah, bl2[0], bl2[1]);
                mma16816(acc[np*2],     al, bh[0], bh[1]);
                mma16816(acc[np*2 + 1], ah, bh[2], bh[3]);
                mma16816(acc[np*2 + 1], ah, bl2[2], bl2[3]);
                mma16816(acc[np*2 + 1], al, bh[2], bh[3]);
            }
        }
        __syncthreads();
    }

    int g = lane >> 2, tg = lane & 3;
    if constexpr (!MLP) {
        float* Crow = p.C + (size_t)(m0 + warp * 16 + g) * p.N + nStrip + tg * 2;
        #pragma unroll
        for (int ng = 0; ng < 8; ng++) {
            *reinterpret_cast<float2*>(Crow + ng * 8) =
                make_float2(acc[ng][0], acc[ng][1]);
            *reinterpret_cast<float2*>(Crow + (size_t)8 * p.N + ng * 8) =
                make_float2(acc[ng][2], acc[ng][3]);
        }
    } else {
        // fused motion MLP: h = relu(G + bm); motion = h @ Wl; dst = cur + bl + motion
        // lane quad (tg=0..3) covers all 64 G-columns for rows g and g+8.
        float m[2][3] = {{0,0,0},{0,0,0}};
        #pragma unroll
        for (int ng = 0; ng < 8; ng++) {
            int j0 = ng * 8 + tg * 2;
            float h00 = fmaxf(acc[ng][0] + __ldg(bm + j0),     0.f);
            float h01 = fmaxf(acc[ng][1] + __ldg(bm + j0 + 1), 0.f);
            float h10 = fmaxf(acc[ng][2] + __ldg(bm + j0),     0.f);
            float h11 = fmaxf(acc[ng][3] + __ldg(bm + j0 + 1), 0.f);
            #pragma unroll
            for (int d = 0; d < 3; d++) {
                float w0 = __ldg(Wl + j0 * 3 + d);
                float w1 = __ldg(Wl + (j0 + 1) * 3 + d);
                m[0][d] += h00 * w0 + h01 * w1;
                m[1][d] += h10 * w0 + h11 * w1;
            }
        }
        #pragma unroll
        for (int r = 0; r < 2; r++)
            #pragma unroll
            for (int d = 0; d < 3; d++) {
                m[r][d] += __shfl_xor_sync(0xFFFFFFFFu, m[r][d], 1);
                m[r][d] += __shfl_xor_sync(0xFFFFFFFFu, m[r][d], 2);
            }
        if (tg == 0) {
            #pragma unroll
            for (int r = 0; r < 2; r++) {
                int p_ = m0 + warp * 16 + g + r * 8;
                int b = p_ >> 9, n = p_ & 511;
                const float* cp = cur + b * cbs + n * 3;
                float*       dp = dst + b * dbs + n * 3;
                #pragma unroll
                for (int d = 0; d < 3; d++)
                    dp[d] = cp[d] + __ldg(bl + d) + m[r][d];
            }
        }
    }
}

__global__ __launch_bounds__(128) void hmma_kernel(HmmaP p0)
{
    __shared__ __align__(16) char sm[SMEM_BYTES];
    hmma_body<false>(p0, sm, nullptr, nullptr, nullptr, nullptr, 0, nullptr, 0);
}

__global__ __launch_bounds__(128) void hmma_mlp_kernel(
    HmmaP p0, const float* bm, const float* Wl, const float* bl,
    const float* cur, int cbs, float* dst, int dbs)
{
    __shared__ __align__(16) char sm[SMEM_BYTES];
    hmma_body<true>(p0, sm, bm, Wl, bl, cur, cbs, dst, dbs);
}

// ---------------------------------------------------------------------------
// Fused step-front: z<3 -> Y GEMMs (HMMA), z==3 -> top-8 (2-way split+merge)
// ---------------------------------------------------------------------------
__global__ __launch_bounds__(128) void front_kernel(
    HmmaP p0, HmmaP p1, HmmaP p2,
    const float* __restrict__ q, int qbs,
    const float* __restrict__ s, int sbs,
    int*   __restrict__ idxOut,
    float* __restrict__ d2Out)
{
    __shared__ __align__(16) char sm[SMEM_BYTES];
    if (blockIdx.z == 3) {
        if (blockIdx.y != 0) return;
        float* sxs = reinterpret_cast<float*>(sm);
        float* sys = sxs + NPTS;
        float* szs = sys + NPTS;
        float* smd = reinterpret_cast<float*>(sm + 6144);        // [2][64][8]
        int*   smi = reinterpret_cast<int*>  (sm + 6144 + 4096); // [2][64][8]

        int b  = blockIdx.x >> 3;
        int n0 = (blockIdx.x & 7) * 64;
        const float* sb = s + b * sbs;
        for (int i = threadIdx.x; i < NPTS; i += 128) {
            sxs[i] = sb[i*3 + 0];
            sys[i] = sb[i*3 + 1];
            szs[i] = sb[i*3 + 2];
        }
        __syncthreads();

        int qi   = threadIdx.x & 63;
        int half = threadIdx.x >> 6;
        int n = n0 + qi;
        const float* qp = q + b * qbs + n * 3;
        float qx = qp[0], qy = qp[1], qz = qp[2];

        float bd[KNN]; int bi[KNN];
        #pragma unroll
        for (int k = 0; k < KNN; k++) { bd[k] = 3.4e38f; bi[k] = 0; }

        int j0 = half * 256;
        for (int j = j0; j < j0 + 256; j++) {
            float dx = __fadd_rn(qx, -sxs[j]);
            float dy = __fadd_rn(qy, -sys[j]);
            float dz = __fadd_rn(qz, -szs[j]);
            float d = __fadd_rn(__fadd_rn(__fmul_rn(dx, dx), __fmul_rn(dy, dy)),
                                __fmul_rn(dz, dz));
            if (d < bd[KNN-1]) {
                bd[KNN-1] = d; bi[KNN-1] = j;
                #pragma unroll
                for (int t = KNN-1; t > 0; --t) {
                    if (bd[t] < bd[t-1]) {
                        float td = bd[t]; bd[t] = bd[t-1]; bd[t-1] = td;
                        int   ti = bi[t]; bi[t] = bi[t-1]; bi[t-1] = ti;
                    }
                }
            }
        }
        #pragma unroll
        for (int k = 0; k < KNN; k++) {
            smd[(half * 64 + qi) * KNN + k] = bd[k];
            smi[(half * 64 + qi) * KNN + k] = bi[k];
        }
        __syncthreads();

        if (threadIdx.x < 64) {
            const float* da = &smd[qi * KNN];
            const int*   ia = &smi[qi * KNN];
            const float* db = &smd[(64 + qi) * KNN];
            const int*   ib = &smi[(64 + qi) * KNN];
            int pa = 0, pb = 0;
            int base = (b * NPTS + n) * KNN;
            #pragma unroll
            for (int k = 0; k < KNN; k++) {
                float va = da[pa], vb = db[pb];
                // tie -> half 0 (lower index), matching lax.top_k stability
                bool takeA = (va <= vb);
                idxOut[base + k] = takeA ? ia[pa] : ib[pb];
                d2Out [base + k] = takeA ? va : vb;
                pa += takeA ? 1 : 0;
                pb += takeA ? 0 : 1;
            }
        }
        return;
    }
    const HmmaP& p = (blockIdx.z == 0) ? p0 : (blockIdx.z == 1) ? p1 : p2;
    hmma_body<false>(p, sm, nullptr, nullptr, nullptr, nullptr, 0, nullptr, 0);
}

// ---------------------------------------------------------------------------
// combine (f32x2) -> bf16 hi/lo state; FUSEQ: Qnext = o_row @ Wnext (fp32)
// ---------------------------------------------------------------------------
template<int C, int P, bool HASQ, bool FUSEQ>
__global__ __launch_bounds__((C/2)*P) void combine_kernel(
    const float* __restrict__ Y,
    const float* __restrict__ Qin,
    const float* __restrict__ W,
    const float* __restrict__ bias,
    const int*   __restrict__ idx,
    const float* __restrict__ d2,
    const float* __restrict__ qx, int qbs,
    const float* __restrict__ sx, int sbs,
    float r2,
    __nv_bfloat16* __restrict__ outH,
    __nv_bfloat16* __restrict__ outL,
    const float* __restrict__ Wnext,
    float* __restrict__ Qnext)
{
    __shared__ int    sRow[P][KNN];
    __shared__ float2 sDX[P][KNN], sDY[P][KNN], sDZ[P][KNN];
    __shared__ float2 frow2[FUSEQ ? P : 1][FUSEQ ? C : 1];
    __shared__ float2 wn2[FUSEQ ? 64 : 1][FUSEQ ? 64 : 1];

    int x = threadIdx.x, y = threadIdx.y;
    int p = blockIdx.x * P + y;
    int b = p >> 9, n = p & 511;

    if (x < KNN) {
        int   raw = idx[p * KNN + x];
        int   i0  = idx[p * KNN];
        float dd  = d2 [p * KNN + x];
        int eff = (dd <= r2) ? raw : i0;
        sRow[y][x] = b * NPTS + eff;
        const float* sp = sx + b * sbs + eff * 3;
        const float* qp = qx + b * qbs + n   * 3;
        float dx = sp[0] - qp[0];
        float dy = sp[1] - qp[1];
        float dz = sp[2] - qp[2];
        sDX[y][x] = make_float2(dx, dx);
        sDY[y][x] = make_float2(dy, dy);
        sDZ[y][x] = make_float2(dz, dz);
    }
    if constexpr (FUSEQ) {
        int tid = y * (C/2) + x;
        #pragma unroll 4
        for (int i = tid; i < 64 * 64; i += (C/2) * P)
            reinterpret_cast<float2*>(wn2)[i] =
                reinterpret_cast<const float2*>(Wnext)[i];
    }
    __syncthreads();

    int j0 = 2 * x;
    ull w0 = *reinterpret_cast<const ull*>(&W[j0]);
    ull w1 = *reinterpret_cast<const ull*>(&W[C + j0]);
    ull w2 = *reinterpret_cast<const ull*>(&W[2*C + j0]);
    float2 bb = *reinterpret_cast<const float2*>(&bias[j0]);

    float mx = -3.4e38f, my = -3.4e38f;
    #pragma unroll
    for (int k = 0; k < KNN; k++) {
        int row = sRow[y][k];
        ull v = *reinterpret_cast<const ull*>(&Y[row * C + j0]);
        ffma2(v, *reinterpret_cast<const ull*>(&sDX[y][k]), w0);
        ffma2(v, *reinterpret_cast<const ull*>(&sDY[y][k]), w1);
        ffma2(v, *reinterpret_cast<const ull*>(&sDZ[y][k]), w2);
        float2 vf = unpk(v);
        mx = fmaxf(mx, vf.x);
        my = fmaxf(my, vf.y);
    }
    float2 o;
    o.x = bb.x + mx;
    o.y = bb.y + my;
    if constexpr (HASQ) {
        float2 qv = *reinterpret_cast<const float2*>(&Qin[p * C + j0]);
        o.x += qv.x; o.y += qv.y;
    }
    {
        __nv_bfloat16 hx = __float2bfloat16_rn(o.x);
        __nv_bfloat16 hy = __float2bfloat16_rn(o.y);
        __nv_bfloat16 lx = __float2bfloat16_rn(o.x - __bfloat162float(hx));
        __nv_bfloat16 ly = __float2bfloat16_rn(o.y - __bfloat162float(hy));
        uint32_t ph = (uint32_t)*reinterpret_cast<uint16_t*>(&hx)
                    | ((uint32_t)*reinterpret_cast<uint16_t*>(&hy) << 16);
        uint32_t pl = (uint32_t)*reinterpret_cast<uint16_t*>(&lx)
                    | ((uint32_t)*reinterpret_cast<uint16_t*>(&ly) << 16);
        *reinterpret_cast<uint32_t*>(&outH[p * C + j0]) = ph;
        *reinterpret_cast<uint32_t*>(&outL[p * C + j0]) = pl;
    }

    if constexpr (FUSEQ) {
        frow2[y][j0]     = make_float2(o.x, o.x);
        frow2[y][j0 + 1] = make_float2(o.y, o.y);
        __syncthreads();
        ull a0 = 0ull, a1 = 0ull;
        #pragma unroll 8
        for (int c = 0; c < C; c++) {
            ull f = *reinterpret_cast<const ull*>(&frow2[y][c]);
            ffma2(a0, f, *reinterpret_cast<const ull*>(&wn2[c][x]));
            ffma2(a1, f, *reinterpret_cast<const ull*>(&wn2[c][x + C/2]));
        }
        float2 q0 = unpk(a0), q1 = unpk(a1);
        *reinterpret_cast<float2*>(&Qnext[p * 128 + j0])     = q0;
        *reinterpret_cast<float2*>(&Qnext[p * 128 + C + j0]) = q1;
    }
}

// ---------------------------------------------------------------------------
// host orchestration
// ---------------------------------------------------------------------------
extern "C" void kernel_launch(void* const* d_in, const int* in_sizes, int n_in,
                              void* d_out, int out_size)
{
    (void)in_sizes; (void)n_in; (void)out_size;

    const float* frames = (const float*)d_in[0];
    const float* W1 = (const float*)d_in[1];
    const float* b1 = (const float*)d_in[2];
    const float* W2 = (const float*)d_in[3];
    const float* b2 = (const float*)d_in[4];
    const float* W3 = (const float*)d_in[5];
    const float* b3 = (const float*)d_in[6];
    const float* Wm = (const float*)d_in[7];
    const float* bm = (const float*)d_in[8];
    const float* Wl = (const float*)d_in[9];
    const float* bl = (const float*)d_in[10];
    float* out = (float*)d_out;

    __nv_bfloat16 *f1h, *f1l, *f2h, *f2l, *f3h, *f3l;
    float *Y1, *Y2, *Y3, *Q2, *Q3;
    int* idxp; float* d2p;
    __nv_bfloat16 *wn1h, *wn1l, *wn2h, *wn2l, *wn3h, *wn3l, *wf3h, *wf3l, *wmh, *wml;
    { void* t;
      cudaGetSymbolAddress(&t, g_f1h); f1h = (__nv_bfloat16*)t;
      cudaGetSymbolAddress(&t, g_f1l); f1l = (__nv_bfloat16*)t;
      cudaGetSymbolAddress(&t, g_f2h); f2h = (__nv_bfloat16*)t;
      cudaGetSymbolAddress(&t, g_f2l); f2l = (__nv_bfloat16*)t;
      cudaGetSymbolAddress(&t, g_f3h); f3h = (__nv_bfloat16*)t;
      cudaGetSymbolAddress(&t, g_f3l); f3l = (__nv_bfloat16*)t;
      cudaGetSymbolAddress(&t, g_Y1); Y1 = (float*)t;
      cudaGetSymbolAddress(&t, g_Y2); Y2 = (float*)t;
      cudaGetSymbolAddress(&t, g_Y3); Y3 = (float*)t;
      cudaGetSymbolAddress(&t, g_Q2); Q2 = (float*)t;
      cudaGetSymbolAddress(&t, g_Q3); Q3 = (float*)t;
      cudaGetSymbolAddress(&t, g_idx); idxp = (int*)t;
      cudaGetSymbolAddress(&t, g_d2);  d2p  = (float*)t;
      cudaGetSymbolAddress(&t, g_Wn1h); wn1h = (__nv_bfloat16*)t;
      cudaGetSymbolAddress(&t, g_Wn1l); wn1l = (__nv_bfloat16*)t;
      cudaGetSymbolAddress(&t, g_Wn2h); wn2h = (__nv_bfloat16*)t;
      cudaGetSymbolAddress(&t, g_Wn2l); wn2l = (__nv_bfloat16*)t;
      cudaGetSymbolAddress(&t, g_Wn3h); wn3h = (__nv_bfloat16*)t;
      cudaGetSymbolAddress(&t, g_Wn3l); wn3l = (__nv_bfloat16*)t;
      cudaGetSymbolAddress(&t, g_Wf3h); wf3h = (__nv_bfloat16*)t;
      cudaGetSymbolAddress(&t, g_Wf3l); wf3l = (__nv_bfloat16*)t;
      cudaGetSymbolAddress(&t, g_Wmh);  wmh  = (__nv_bfloat16*)t;
      cudaGetSymbolAddress(&t, g_Wml);  wml  = (__nv_bfloat16*)t;
    }

    const int FBS = SEQ * NPTS * 3;
    const int OBS = HALF * NPTS * 3;
    const int FRM = NPTS * 3;

    const double R0 = 4.0 + 1e-6, R1 = 8.0 + 1e-6, R2 = 12.0 + 1e-6;
    const float r2c1 = (float)(R0 * R0);
    const float r2c2 = (float)(R1 * R1);
    const float r2c3 = (float)(R2 * R2);

    const float* Wn1 = W1 + 3 * 64;
    const float* Wf2 = W2 + 3 * 128;
    const float* Wn2 = W2 + (3 + 64) * 128;
    const float* Wf3 = W3 + 3 * 256;
    const float* Wn3 = W3 + (3 + 128) * 256;

    init_kernel<<<512, 256>>>(Wn1, Wn2, Wn3, Wf3, Wm);

    for (int t = 0; t < SEQ; t++) {
        const float *q, *s; int qbs, sbs;
        if (t < HALF) {
            q = frames + t * FRM;                       qbs = FBS;
            s = frames + (t ? (t - 1) : 0) * FRM;       sbs = FBS;
        } else if (t == HALF) {
            q = frames + (HALF - 1) * FRM;              qbs = FBS;
            s = q;                                      sbs = FBS;
        } else if (t == HALF + 1) {
            q = out;                                    qbs = OBS;
            s = frames + (HALF - 1) * FRM;              sbs = FBS;
        } else {
            q = out + (t - HALF - 1) * FRM;             qbs = OBS;
            s = out + (t - HALF - 2) * FRM;             sbs = OBS;
        }

        int pin = t & 1, pout = 1 - pin;
        __nv_bfloat16* f1ih = f1h + pin  * BNT * 64;
        __nv_bfloat16* f1il = f1l + pin  * BNT * 64;
        __nv_bfloat16* f1oh = f1h + pout * BNT * 64;
        __nv_bfloat16* f1ol = f1l + pout * BNT * 64;
        __nv_bfloat16* f2ih = f2h + pin  * BNT * 128;
        __nv_bfloat16* f2il = f2l + pin  * BNT * 128;
        __nv_bfloat16* f2oh = f2h + pout * BNT * 128;
        __nv_bfloat16* f2ol = f2l + pout * BNT * 128;
        __nv_bfloat16* f3ih = f3h + pin  * BNT * 256;
        __nv_bfloat16* f3il = f3l + pin  * BNT * 256;
        __nv_bfloat16* f3oh = f3h + pout * BNT * 256;
        __nv_bfloat16* f3ol = f3l + pout * BNT * 256;

        // 1) fused: topk + Y GEMMs (HMMA)
        HmmaP y1 = { f1ih, f1il, wn1h, wn1l, Y1, 64, 64 };
        HmmaP y2 = { f2ih, f2il, wn2h, wn2l, Y2, 128, 128 };
        HmmaP y3 = { f3ih, f3il, wn3h, wn3l, Y3, 256, 256 };
        front_kernel<<<dim3(128, 4, 4), 128>>>(
            y1, y2, y3, q, qbs, s, sbs, idxp, d2p);

        // 2) cell 1 combine + fused Q2 = f1o @ Wf2 (fp32 exact)
        combine_kernel<64, 8, false, true><<<BNT / 8, dim3(32, 8)>>>(
            Y1, nullptr, W1, b1, idxp, d2p, q, qbs, s, sbs, r2c1,
            f1oh, f1ol, Wf2, Q2);

        // 3) cell 2 combine
        combine_kernel<128, 4, true, false><<<BNT / 4, dim3(64, 4)>>>(
            Y2, Q2, W2, b2, idxp, d2p, q, qbs, s, sbs, r2c2,
            f2oh, f2ol, nullptr, nullptr);

        // 4) Q3 = f2o @ Wf3 (HMMA)
        HmmaP q3d = { f2oh, f2ol, wf3h, wf3l, Q3, 256, 128 };
        hmma_kernel<<<dim3(128, 4), 128>>>(q3d);

        // 5) cell 3 combine
        combine_kernel<256, 2, true, false><<<BNT / 2, dim3(128, 2)>>>(
            Y3, Q3, W3, b3, idxp, d2p, q, qbs, s, sbs, r2c3,
            f3oh, f3ol, nullptr, nullptr);

        // 6) prediction: G GEMM + fused motion MLP + frame update
        if (t >= HALF) {
            HmmaP gm = { f3oh, f3ol, wmh, wml, nullptr, 64, 256 };
            hmma_mlp_kernel<<<dim3(128, 1), 128>>>(
                gm, bm, Wl, bl, q, qbs, out + (t - HALF) * FRM, OBS);
        }
    }
}

// round 7
// speedup vs baseline: 1.5339x; 1.0083x over previous
#include <cuda_runtime.h>
#include <cuda_bf16.h>
#include <cstdint>

typedef unsigned long long ull;

#define NB    16
#define NPTS  512
#define BNT   (NB*NPTS)   // 8192
#define KNN   8
#define SEQ   12
#define HALF  6

// ---------------------------------------------------------------------------
// Scratch (static device globals)
// ---------------------------------------------------------------------------
__device__ __align__(16) __nv_bfloat16 g_f1h[2 * BNT * 64],  g_f1l[2 * BNT * 64];
__device__ __align__(16) __nv_bfloat16 g_f2h[2 * BNT * 128], g_f2l[2 * BNT * 128];
__device__ __align__(16) __nv_bfloat16 g_f3h[2 * BNT * 256], g_f3l[2 * BNT * 256];
__device__ __align__(16) float g_Z1[BNT * 64];    // Y + s.Wd  (cell 1)
__device__ __align__(16) float g_Z2[BNT * 128];
__device__ __align__(16) float g_Z3[BNT * 256];
__device__ __align__(16) float g_Q2[BNT * 128];
__device__ __align__(16) float g_Q3[BNT * 256];
__device__ __align__(16) int   g_idx[BNT * KNN];
__device__ __align__(16) float g_d2 [BNT * KNN];
__device__ __align__(16) __nv_bfloat16 g_Wn1h[64*64],   g_Wn1l[64*64];
__device__ __align__(16) __nv_bfloat16 g_Wn2h[128*128], g_Wn2l[128*128];
__device__ __align__(16) __nv_bfloat16 g_Wn3h[256*256], g_Wn3l[256*256];
__device__ __align__(16) __nv_bfloat16 g_Wf3h[128*256], g_Wf3l[128*256];
__device__ __align__(16) __nv_bfloat16 g_Wmh [256*64],  g_Wml [256*64];

// ---------------------------------------------------------------------------
// packed f32x2 helpers
// ---------------------------------------------------------------------------
__device__ __forceinline__ void ffma2(ull& d, ull a, ull b)
{
    asm("fma.rn.f32x2 %0, %1, %2, %0;" : "+l"(d) : "l"(a), "l"(b));
}
__device__ __forceinline__ float2 unpk(ull v)
{
    float2 f;
    asm("mov.b64 {%0, %1}, %2;" : "=f"(f.x), "=f"(f.y) : "l"(v));
    return f;
}

// ---------------------------------------------------------------------------
// HMMA primitives
// ---------------------------------------------------------------------------
__device__ __forceinline__ uint32_t smem_u32(const void* p)
{
    uint32_t a;
    asm("{ .reg .u64 t; cvta.to.shared.u64 t, %1; cvt.u32.u64 %0, t; }"
        : "=r"(a) : "l"(p));
    return a;
}
__device__ __forceinline__ void ldsm4(uint32_t* r, uint32_t a)
{
    asm volatile("ldmatrix.sync.aligned.m8n8.x4.shared.b16 {%0,%1,%2,%3}, [%4];"
        : "=r"(r[0]), "=r"(r[1]), "=r"(r[2]), "=r"(r[3]) : "r"(a));
}
__device__ __forceinline__ void ldsm4t(uint32_t* r, uint32_t a)
{
    asm volatile("ldmatrix.sync.aligned.m8n8.x4.trans.shared.b16 {%0,%1,%2,%3}, [%4];"
        : "=r"(r[0]), "=r"(r[1]), "=r"(r[2]), "=r"(r[3]) : "r"(a));
}
__device__ __forceinline__ void mma16816(float* d, const uint32_t* a,
                                         uint32_t b0, uint32_t b1)
{
    asm volatile(
        "mma.sync.aligned.m16n8k16.row.col.f32.bf16.bf16.f32 "
        "{%0,%1,%2,%3}, {%4,%5,%6,%7}, {%8,%9}, {%0,%1,%2,%3};"
        : "+f"(d[0]), "+f"(d[1]), "+f"(d[2]), "+f"(d[3])
        : "r"(a[0]), "r"(a[1]), "r"(a[2]), "r"(a[3]), "r"(b0), "r"(b1));
}

// ---------------------------------------------------------------------------
// single init kernel: zero states + all 5 weight hi/lo conversions
// ---------------------------------------------------------------------------
__device__ __forceinline__ void wsplit(const float* W, __nv_bfloat16* hi,
                                       __nv_bfloat16* lo, int total,
                                       int i0, int stride)
{
    for (int i = i0; i < total; i += stride) {
        float x = W[i];
        __nv_bfloat16 h = __float2bfloat16_rn(x);
        __nv_bfloat16 l = __float2bfloat16_rn(x - __bfloat162float(h));
        hi[i] = h;
        lo[i] = l;
    }
}

__global__ void init_kernel(const float* __restrict__ Wn1,
                            const float* __restrict__ Wn2,
                            const float* __restrict__ Wn3,
                            const float* __restrict__ Wf3,
                            const float* __restrict__ Wm)
{
    int stride = gridDim.x * blockDim.x;
    int i0 = blockIdx.x * blockDim.x + threadIdx.x;
    uint32_t* a;
    a = reinterpret_cast<uint32_t*>(g_f1h);
    for (int i = i0; i < BNT * 64;  i += stride) a[i] = 0u;
    a = reinterpret_cast<uint32_t*>(g_f1l);
    for (int i = i0; i < BNT * 64;  i += stride) a[i] = 0u;
    a = reinterpret_cast<uint32_t*>(g_f2h);
    for (int i = i0; i < BNT * 128; i += stride) a[i] = 0u;
    a = reinterpret_cast<uint32_t*>(g_f2l);
    for (int i = i0; i < BNT * 128; i += stride) a[i] = 0u;
    a = reinterpret_cast<uint32_t*>(g_f3h);
    for (int i = i0; i < BNT * 256; i += stride) a[i] = 0u;
    a = reinterpret_cast<uint32_t*>(g_f3l);
    for (int i = i0; i < BNT * 256; i += stride) a[i] = 0u;

    wsplit(Wn1, g_Wn1h, g_Wn1l, 64*64,   i0, stride);
    wsplit(Wn2, g_Wn2h, g_Wn2l, 128*128, i0, stride);
    wsplit(Wn3, g_Wn3h, g_Wn3l, 256*256, i0, stride);
    wsplit(Wf3, g_Wf3h, g_Wf3l, 128*256, i0, stride);
    wsplit(Wm,  g_Wmh,  g_Wml,  256*64,  i0, stride);
}

// ---------------------------------------------------------------------------
// Split-bf16 HMMA GEMM body. MODE 0: plain store. MODE 1: Z-epilogue
// (C[row][col] = acc + s_xyz[row].Wd[:,col]). MODE 2: fused motion MLP.
// ---------------------------------------------------------------------------
struct HmmaP {
    const __nv_bfloat16 *Ah, *Al, *Bh, *Bl;
    float* C;
    int N, K;
};

#define SMEM_BYTES 19456

template<int MODE>
__device__ __forceinline__ void hmma_body(const HmmaP& p, char* sm,
    const float* sxyz, int sbs, const float* Wfull,            // MODE 1
    const float* bm, const float* Wl, const float* bl,         // MODE 2
    const float* cur, int cbs, float* dst, int dbs)
{
    int nStrip = blockIdx.y * 64;
    if (nStrip >= p.N) return;

    __nv_bfloat16 (*sAh)[40] = reinterpret_cast<__nv_bfloat16(*)[40]>(sm);
    __nv_bfloat16 (*sAl)[40] = reinterpret_cast<__nv_bfloat16(*)[40]>(sm + 5120);
    __nv_bfloat16 (*sBh)[72] = reinterpret_cast<__nv_bfloat16(*)[72]>(sm + 10240);
    __nv_bfloat16 (*sBl)[72] = reinterpret_cast<__nv_bfloat16(*)[72]>(sm + 14848);

    int tid = threadIdx.x, warp = tid >> 5, lane = tid & 31;
    int m0 = blockIdx.x * 64;

    float acc[8][4];
    #pragma unroll
    for (int i = 0; i < 8; i++)
        #pragma unroll
        for (int j = 0; j < 4; j++) acc[i][j] = 0.f;

    int aRow = warp * 16 + (lane & 15);
    int hi8  = (lane >> 4) * 8;
    int bRow = lane & 15;

    for (int k0 = 0; k0 < p.K; k0 += 32) {
        #pragma unroll
        for (int i = 0; i < 2; i++) {
            int id = tid + i * 128;
            int r = id >> 2, c = (id & 3) * 8;
            const __nv_bfloat16* gh = p.Ah + (size_t)(m0 + r) * p.K + k0 + c;
            const __nv_bfloat16* gl = p.Al + (size_t)(m0 + r) * p.K + k0 + c;
            *reinterpret_cast<uint4*>(&sAh[r][c]) = *reinterpret_cast<const uint4*>(gh);
            *reinterpret_cast<uint4*>(&sAl[r][c]) = *reinterpret_cast<const uint4*>(gl);
        }
        #pragma unroll
        for (int i = 0; i < 2; i++) {
            int id = tid + i * 128;
            int r = id >> 3, c = (id & 7) * 8;
            const __nv_bfloat16* gh = p.Bh + (size_t)(k0 + r) * p.N + nStrip + c;
            const __nv_bfloat16* gl = p.Bl + (size_t)(k0 + r) * p.N + nStrip + c;
            *reinterpret_cast<uint4*>(&sBh[r][c]) = *reinterpret_cast<const uint4*>(gh);
            *reinterpret_cast<uint4*>(&sBl[r][c]) = *reinterpret_cast<const uint4*>(gl);
        }
        __syncthreads();

        #pragma unroll
        for (int kk = 0; kk < 32; kk += 16) {
            uint32_t ah[4], al[4];
            ldsm4(ah, smem_u32(&sAh[aRow][kk + hi8]));
            ldsm4(al, smem_u32(&sAl[aRow][kk + hi8]));
            #pragma unroll
            for (int np = 0; np < 4; np++) {
                uint32_t bh[4], bl2[4];
                ldsm4t(bh,  smem_u32(&sBh[kk + bRow][np * 16 + hi8]));
                ldsm4t(bl2, smem_u32(&sBl[kk + bRow][np * 16 + hi8]));
                mma16816(acc[np*2],     ah, bh[0], bh[1]);
                mma16816(acc[np*2],     ah, bl2[0], bl2[1]);
                mma16816(acc[np*2],     al, bh[0], bh[1]);
                mma16816(acc[np*2 + 1], ah, bh[2], bh[3]);
                mma16816(acc[np*2 + 1], ah, bl2[2], bl2[3]);
                mma16816(acc[np*2 + 1], al, bh[2], bh[3]);
            }
        }
        __syncthreads();
    }

    int g = lane >> 2, tg = lane & 3;
    if constexpr (MODE == 0) {
        float* Crow = p.C + (size_t)(m0 + warp * 16 + g) * p.N + nStrip + tg * 2;
        #pragma unroll
        for (int ng = 0; ng < 8; ng++) {
            *reinterpret_cast<float2*>(Crow + ng * 8) =
                make_float2(acc[ng][0], acc[ng][1]);
            *reinterpret_cast<float2*>(Crow + (size_t)8 * p.N + ng * 8) =
                make_float2(acc[ng][2], acc[ng][3]);
        }
    } else if constexpr (MODE == 1) {
        // Z = GEMM + s_xyz[row] . Wd[:, col]
        int p0_ = m0 + warp * 16 + g;
        int p1_ = p0_ + 8;
        int b0 = p0_ >> 9, n0 = p0_ & 511;
        int b1 = p1_ >> 9, n1 = p1_ & 511;
        const float* sp0 = sxyz + b0 * sbs + n0 * 3;
        const float* sp1 = sxyz + b1 * sbs + n1 * 3;
        float s00 = sp0[0], s01 = sp0[1], s02 = sp0[2];
        float s10 = sp1[0], s11 = sp1[1], s12 = sp1[2];
        float* Crow = p.C + (size_t)p0_ * p.N + nStrip + tg * 2;
        #pragma unroll
        for (int ng = 0; ng < 8; ng++) {
            int col = nStrip + ng * 8 + tg * 2;
            float w00 = __ldg(Wfull + col),           w01 = __ldg(Wfull + col + 1);
            float w10 = __ldg(Wfull + p.N + col),     w11 = __ldg(Wfull + p.N + col + 1);
            float w20 = __ldg(Wfull + 2 * p.N + col), w21 = __ldg(Wfull + 2 * p.N + col + 1);
            float a0 = s00 * w00 + s01 * w10 + s02 * w20;
            float a1 = s00 * w01 + s01 * w11 + s02 * w21;
            float c0 = s10 * w00 + s11 * w10 + s12 * w20;
            float c1 = s10 * w01 + s11 * w11 + s12 * w21;
            *reinterpret_cast<float2*>(Crow + ng * 8) =
                make_float2(acc[ng][0] + a0, acc[ng][1] + a1);
            *reinterpret_cast<float2*>(Crow + (size_t)8 * p.N + ng * 8) =
                make_float2(acc[ng][2] + c0, acc[ng][3] + c1);
        }
    } else {
        // fused motion MLP
        float m[2][3] = {{0,0,0},{0,0,0}};
        #pragma unroll
        for (int ng = 0; ng < 8; ng++) {
            int j0 = ng * 8 + tg * 2;
            float h00 = fmaxf(acc[ng][0] + __ldg(bm + j0),     0.f);
            float h01 = fmaxf(acc[ng][1] + __ldg(bm + j0 + 1), 0.f);
            float h10 = fmaxf(acc[ng][2] + __ldg(bm + j0),     0.f);
            float h11 = fmaxf(acc[ng][3] + __ldg(bm + j0 + 1), 0.f);
            #pragma unroll
            for (int d = 0; d < 3; d++) {
                float w0 = __ldg(Wl + j0 * 3 + d);
                float w1 = __ldg(Wl + (j0 + 1) * 3 + d);
                m[0][d] += h00 * w0 + h01 * w1;
                m[1][d] += h10 * w0 + h11 * w1;
            }
        }
        #pragma unroll
        for (int r = 0; r < 2; r++)
            #pragma unroll
            for (int d = 0; d < 3; d++) {
                m[r][d] += __shfl_xor_sync(0xFFFFFFFFu, m[r][d], 1);
                m[r][d] += __shfl_xor_sync(0xFFFFFFFFu, m[r][d], 2);
            }
        if (tg == 0) {
            #pragma unroll
            for (int r = 0; r < 2; r++) {
                int p_ = m0 + warp * 16 + g + r * 8;
                int b = p_ >> 9, n = p_ & 511;
                const float* cp = cur + b * cbs + n * 3;
                float*       dp = dst + b * dbs + n * 3;
                #pragma unroll
                for (int d = 0; d < 3; d++)
                    dp[d] = cp[d] + __ldg(bl + d) + m[r][d];
            }
        }
    }
}

__global__ __launch_bounds__(128) void hmma_kernel(HmmaP p0)
{
    __shared__ __align__(16) char sm[SMEM_BYTES];
    hmma_body<0>(p0, sm, nullptr, 0, nullptr,
                 nullptr, nullptr, nullptr, nullptr, 0, nullptr, 0);
}

__global__ __launch_bounds__(128) void hmma_mlp_kernel(
    HmmaP p0, const float* bm, const float* Wl, const float* bl,
    const float* cur, int cbs, float* dst, int dbs)
{
    __shared__ __align__(16) char sm[SMEM_BYTES];
    hmma_body<2>(p0, sm, nullptr, 0, nullptr, bm, Wl, bl, cur, cbs, dst, dbs);
}

// ---------------------------------------------------------------------------
// Fused step-front: z<3 -> Z GEMMs (HMMA + s.Wd epilogue), z==3 -> top-8
// ---------------------------------------------------------------------------
__global__ __launch_bounds__(128) void front_kernel(
    HmmaP p0, HmmaP p1, HmmaP p2,
    const float* __restrict__ W1, const float* __restrict__ W2,
    const float* __restrict__ W3,
    const float* __restrict__ q, int qbs,
    const float* __restrict__ s, int sbs,
    int*   __restrict__ idxOut,
    float* __restrict__ d2Out)
{
    __shared__ __align__(16) char sm[SMEM_BYTES];
    if (blockIdx.z == 3) {
        if (blockIdx.y != 0) return;
        float* sxs = reinterpret_cast<float*>(sm);
        float* sys = sxs + NPTS;
        float* szs = sys + NPTS;
        float* smd = reinterpret_cast<float*>(sm + 6144);        // [2][64][8]
        int*   smi = reinterpret_cast<int*>  (sm + 6144 + 4096); // [2][64][8]

        int b  = blockIdx.x >> 3;
        int n0 = (blockIdx.x & 7) * 64;
        const float* sb = s + b * sbs;
        for (int i = threadIdx.x; i < NPTS; i += 128) {
            sxs[i] = sb[i*3 + 0];
            sys[i] = sb[i*3 + 1];
            szs[i] = sb[i*3 + 2];
        }
        __syncthreads();

        int qi   = threadIdx.x & 63;
        int half = threadIdx.x >> 6;
        int n = n0 + qi;
        const float* qp = q + b * qbs + n * 3;
        float qx = qp[0], qy = qp[1], qz = qp[2];

        float bd[KNN]; int bi[KNN];
        #pragma unroll
        for (int k = 0; k < KNN; k++) { bd[k] = 3.4e38f; bi[k] = 0; }

        int j0 = half * 256;
        for (int j = j0; j < j0 + 256; j++) {
            float dx = __fadd_rn(qx, -sxs[j]);
            float dy = __fadd_rn(qy, -sys[j]);
            float dz = __fadd_rn(qz, -szs[j]);
            float d = __fadd_rn(__fadd_rn(__fmul_rn(dx, dx), __fmul_rn(dy, dy)),
                                __fmul_rn(dz, dz));
            if (d < bd[KNN-1]) {
                bd[KNN-1] = d; bi[KNN-1] = j;
                #pragma unroll
                for (int t = KNN-1; t > 0; --t) {
                    if (bd[t] < bd[t-1]) {
                        float td = bd[t]; bd[t] = bd[t-1]; bd[t-1] = td;
                        int   ti = bi[t]; bi[t] = bi[t-1]; bi[t-1] = ti;
                    }
                }
            }
        }
        #pragma unroll
        for (int k = 0; k < KNN; k++) {
            smd[(half * 64 + qi) * KNN + k] = bd[k];
            smi[(half * 64 + qi) * KNN + k] = bi[k];
        }
        __syncthreads();

        if (threadIdx.x < 64) {
            const float* da = &smd[qi * KNN];
            const int*   ia = &smi[qi * KNN];
            const float* db = &smd[(64 + qi) * KNN];
            const int*   ib = &smi[(64 + qi) * KNN];
            int pa = 0, pb = 0;
            int base = (b * NPTS + n) * KNN;
            #pragma unroll
            for (int k = 0; k < KNN; k++) {
                float va = da[pa], vb = db[pb];
                bool takeA = (va <= vb);   // tie -> lower index (half 0)
                idxOut[base + k] = takeA ? ia[pa] : ib[pb];
                d2Out [base + k] = takeA ? va : vb;
                pa += takeA ? 1 : 0;
                pb += takeA ? 0 : 1;
            }
        }
        return;
    }
    const HmmaP& p = (blockIdx.z == 0) ? p0 : (blockIdx.z == 1) ? p1 : p2;
    const float* Wf = (blockIdx.z == 0) ? W1 : (blockIdx.z == 1) ? W2 : W3;
    hmma_body<1>(p, sm, s, sbs, Wf,
                 nullptr, nullptr, nullptr, nullptr, 0, nullptr, 0);
}

// ---------------------------------------------------------------------------
// combine: o[p,j] = bias[j] + Q[p,j] - q_xyz[p].Wd[:,j] + max_k Z[row_k,j]
// -> bf16 hi/lo state. FUSEQ: Qnext = o_row @ Wnext (fp32, smem).
// ---------------------------------------------------------------------------
template<int C, int P, bool HASQ, bool FUSEQ>
__global__ __launch_bounds__((C/2)*P) void combine_kernel(
    const float* __restrict__ Z,
    const float* __restrict__ Qin,
    const float* __restrict__ W,
    const float* __restrict__ bias,
    const int*   __restrict__ idx,
    const float* __restrict__ d2,
    const float* __restrict__ qx, int qbs,
    float r2,
    __nv_bfloat16* __restrict__ outH,
    __nv_bfloat16* __restrict__ outL,
    const float* __restrict__ Wnext,
    float* __restrict__ Qnext)
{
    __shared__ int    sRow[P][KNN];
    __shared__ float2 frow2[FUSEQ ? P : 1][FUSEQ ? C : 1];
    __shared__ float2 wn2[FUSEQ ? 64 : 1][FUSEQ ? 64 : 1];

    int x = threadIdx.x, y = threadIdx.y;
    int p = blockIdx.x * P + y;
    int b = p >> 9, n = p & 511;

    if (x < KNN) {
        int   raw = idx[p * KNN + x];
        int   i0  = idx[p * KNN];
        float dd  = d2 [p * KNN + x];
        int eff = (dd <= r2) ? raw : i0;
        sRow[y][x] = b * NPTS + eff;
    }
    if constexpr (FUSEQ) {
        int tid = y * (C/2) + x;
        #pragma unroll 4
        for (int i = tid; i < 64 * 64; i += (C/2) * P)
            reinterpret_cast<float2*>(wn2)[i] =
                reinterpret_cast<const float2*>(Wnext)[i];
    }
    __syncthreads();

    int j0 = 2 * x;
    float2 w0 = *reinterpret_cast<const float2*>(&W[j0]);
    float2 w1 = *reinterpret_cast<const float2*>(&W[C + j0]);
    float2 w2 = *reinterpret_cast<const float2*>(&W[2*C + j0]);
    float2 bb = *reinterpret_cast<const float2*>(&bias[j0]);

    const float* qp = qx + b * qbs + n * 3;
    float q0 = qp[0], q1 = qp[1], q2v = qp[2];
    float tx = q0 * w0.x + q1 * w1.x + q2v * w2.x;
    float ty = q0 * w0.y + q1 * w1.y + q2v * w2.y;

    float mx = -3.4e38f, my = -3.4e38f;
    #pragma unroll
    for (int k = 0; k < KNN; k++) {
        int row = sRow[y][k];
        float2 zf = unpk(__ldg(reinterpret_cast<const ull*>(&Z[row * C + j0])));
        mx = fmaxf(mx, zf.x);
        my = fmaxf(my, zf.y);
    }
    float2 o;
    o.x = bb.x + (mx - tx);
    o.y = bb.y + (my - ty);
    if constexpr (HASQ) {
        float2 qv = *reinterpret_cast<const float2*>(&Qin[p * C + j0]);
        o.x += qv.x; o.y += qv.y;
    }
    {
        __nv_bfloat16 hx = __float2bfloat16_rn(o.x);
        __nv_bfloat16 hy = __float2bfloat16_rn(o.y);
        __nv_bfloat16 lx = __float2bfloat16_rn(o.x - __bfloat162float(hx));
        __nv_bfloat16 ly = __float2bfloat16_rn(o.y - __bfloat162float(hy));
        uint32_t ph = (uint32_t)*reinterpret_cast<uint16_t*>(&hx)
                    | ((uint32_t)*reinterpret_cast<uint16_t*>(&hy) << 16);
        uint32_t pl = (uint32_t)*reinterpret_cast<uint16_t*>(&lx)
                    | ((uint32_t)*reinterpret_cast<uint16_t*>(&ly) << 16);
        *reinterpret_cast<uint32_t*>(&outH[p * C + j0]) = ph;
        *reinterpret_cast<uint32_t*>(&outL[p * C + j0]) = pl;
    }

    if constexpr (FUSEQ) {
        frow2[y][j0]     = make_float2(o.x, o.x);
        frow2[y][j0 + 1] = make_float2(o.y, o.y);
        __syncthreads();
        ull a0 = 0ull, a1 = 0ull;
        #pragma unroll 8
        for (int c = 0; c < C; c++) {
            ull f = *reinterpret_cast<const ull*>(&frow2[y][c]);
            ffma2(a0, f, *reinterpret_cast<const ull*>(&wn2[c][x]));
            ffma2(a1, f, *reinterpret_cast<const ull*>(&wn2[c][x + C/2]));
        }
        float2 qo0 = unpk(a0), qo1 = unpk(a1);
        *reinterpret_cast<float2*>(&Qnext[p * 128 + j0])     = qo0;
        *reinterpret_cast<float2*>(&Qnext[p * 128 + C + j0]) = qo1;
    }
}

// ---------------------------------------------------------------------------
// host orchestration
// ---------------------------------------------------------------------------
extern "C" void kernel_launch(void* const* d_in, const int* in_sizes, int n_in,
                              void* d_out, int out_size)
{
    (void)in_sizes; (void)n_in; (void)out_size;

    const float* frames = (const float*)d_in[0];
    const float* W1 = (const float*)d_in[1];
    const float* b1 = (const float*)d_in[2];
    const float* W2 = (const float*)d_in[3];
    const float* b2 = (const float*)d_in[4];
    const float* W3 = (const float*)d_in[5];
    const float* b3 = (const float*)d_in[6];
    const float* Wm = (const float*)d_in[7];
    const float* bm = (const float*)d_in[8];
    const float* Wl = (const float*)d_in[9];
    const float* bl = (const float*)d_in[10];
    float* out = (float*)d_out;

    __nv_bfloat16 *f1h, *f1l, *f2h, *f2l, *f3h, *f3l;
    float *Z1, *Z2, *Z3, *Q2, *Q3;
    int* idxp; float* d2p;
    __nv_bfloat16 *wn1h, *wn1l, *wn2h, *wn2l, *wn3h, *wn3l, *wf3h, *wf3l, *wmh, *wml;
    { void* t;
      cudaGetSymbolAddress(&t, g_f1h); f1h = (__nv_bfloat16*)t;
      cudaGetSymbolAddress(&t, g_f1l); f1l = (__nv_bfloat16*)t;
      cudaGetSymbolAddress(&t, g_f2h); f2h = (__nv_bfloat16*)t;
      cudaGetSymbolAddress(&t, g_f2l); f2l = (__nv_bfloat16*)t;
      cudaGetSymbolAddress(&t, g_f3h); f3h = (__nv_bfloat16*)t;
      cudaGetSymbolAddress(&t, g_f3l); f3l = (__nv_bfloat16*)t;
      cudaGetSymbolAddress(&t, g_Z1); Z1 = (float*)t;
      cudaGetSymbolAddress(&t, g_Z2); Z2 = (float*)t;
      cudaGetSymbolAddress(&t, g_Z3); Z3 = (float*)t;
      cudaGetSymbolAddress(&t, g_Q2); Q2 = (float*)t;
      cudaGetSymbolAddress(&t, g_Q3); Q3 = (float*)t;
      cudaGetSymbolAddress(&t, g_idx); idxp = (int*)t;
      cudaGetSymbolAddress(&t, g_d2);  d2p  = (float*)t;
      cudaGetSymbolAddress(&t, g_Wn1h); wn1h = (__nv_bfloat16*)t;
      cudaGetSymbolAddress(&t, g_Wn1l); wn1l = (__nv_bfloat16*)t;
      cudaGetSymbolAddress(&t, g_Wn2h); wn2h = (__nv_bfloat16*)t;
      cudaGetSymbolAddress(&t, g_Wn2l); wn2l = (__nv_bfloat16*)t;
      cudaGetSymbolAddress(&t, g_Wn3h); wn3h = (__nv_bfloat16*)t;
      cudaGetSymbolAddress(&t, g_Wn3l); wn3l = (__nv_bfloat16*)t;
      cudaGetSymbolAddress(&t, g_Wf3h); wf3h = (__nv_bfloat16*)t;
      cudaGetSymbolAddress(&t, g_Wf3l); wf3l = (__nv_bfloat16*)t;
      cudaGetSymbolAddress(&t, g_Wmh);  wmh  = (__nv_bfloat16*)t;
      cudaGetSymbolAddress(&t, g_Wml);  wml  = (__nv_bfloat16*)t;
    }

    const int FBS = SEQ * NPTS * 3;
    const int OBS = HALF * NPTS * 3;
    const int FRM = NPTS * 3;

    const double R0 = 4.0 + 1e-6, R1 = 8.0 + 1e-6, R2 = 12.0 + 1e-6;
    const float r2c1 = (float)(R0 * R0);
    const float r2c2 = (float)(R1 * R1);
    const float r2c3 = (float)(R2 * R2);

    const float* Wn1 = W1 + 3 * 64;
    const float* Wf2 = W2 + 3 * 128;
    const float* Wn2 = W2 + (3 + 64) * 128;
    const float* Wf3 = W3 + 3 * 256;
    const float* Wn3 = W3 + (3 + 128) * 256;

    init_kernel<<<512, 256>>>(Wn1, Wn2, Wn3, Wf3, Wm);

    for (int t = 0; t < SEQ; t++) {
        const float *q, *s; int qbs, sbs;
        if (t < HALF) {
            q = frames + t * FRM;                       qbs = FBS;
            s = frames + (t ? (t - 1) : 0) * FRM;       sbs = FBS;
        } else if (t == HALF) {
            q = frames + (HALF - 1) * FRM;              qbs = FBS;
            s = q;                                      sbs = FBS;
        } else if (t == HALF + 1) {
            q = out;                                    qbs = OBS;
            s = frames + (HALF - 1) * FRM;              sbs = FBS;
        } else {
            q = out + (t - HALF - 1) * FRM;             qbs = OBS;
            s = out + (t - HALF - 2) * FRM;             sbs = OBS;
        }

        int pin = t & 1, pout = 1 - pin;
        __nv_bfloat16* f1ih = f1h + pin  * BNT * 64;
        __nv_bfloat16* f1il = f1l + pin  * BNT * 64;
        __nv_bfloat16* f1oh = f1h + pout * BNT * 64;
        __nv_bfloat16* f1ol = f1l + pout * BNT * 64;
        __nv_bfloat16* f2ih = f2h + pin  * BNT * 128;
        __nv_bfloat16* f2il = f2l + pin  * BNT * 128;
        __nv_bfloat16* f2oh = f2h + pout * BNT * 128;
        __nv_bfloat16* f2ol = f2l + pout * BNT * 128;
        __nv_bfloat16* f3ih = f3h + pin  * BNT * 256;
        __nv_bfloat16* f3il = f3l + pin  * BNT * 256;
        __nv_bfloat16* f3oh = f3h + pout * BNT * 256;
        __nv_bfloat16* f3ol = f3l + pout * BNT * 256;

        // 1) fused: topk + Z GEMMs (HMMA + s.Wd epilogue)
        HmmaP y1 = { f1ih, f1il, wn1h, wn1l, Z1, 64, 64 };
        HmmaP y2 = { f2ih, f2il, wn2h, wn2l, Z2, 128, 128 };
        HmmaP y3 = { f3ih, f3il, wn3h, wn3l, Z3, 256, 256 };
        front_kernel<<<dim3(128, 4, 4), 128>>>(
            y1, y2, y3, W1, W2, W3, q, qbs, s, sbs, idxp, d2p);

        // 2) cell 1 combine + fused Q2 = f1o @ Wf2 (fp32 exact)
        combine_kernel<64, 8, false, true><<<BNT / 8, dim3(32, 8)>>>(
            Z1, nullptr, W1, b1, idxp, d2p, q, qbs, r2c1,
            f1oh, f1ol, Wf2, Q2);

        // 3) cell 2 combine
        combine_kernel<128, 4, true, false><<<BNT / 4, dim3(64, 4)>>>(
            Z2, Q2, W2, b2, idxp, d2p, q, qbs, r2c2,
            f2oh, f2ol, nullptr, nullptr);

        // 4) Q3 = f2o @ Wf3 (HMMA)
        HmmaP q3d = { f2oh, f2ol, wf3h, wf3l, Q3, 256, 128 };
        hmma_kernel<<<dim3(128, 4), 128>>>(q3d);

        // 5) cell 3 combine
        combine_kernel<256, 2, true, false><<<BNT / 2, dim3(128, 2)>>>(
            Z3, Q3, W3, b3, idxp, d2p, q, qbs, r2c3,
            f3oh, f3ol, nullptr, nullptr);

        // 6) prediction: G GEMM + fused motion MLP + frame update
        if (t >= HALF) {
            HmmaP gm = { f3oh, f3ol, wmh, wml, nullptr, 64, 256 };
            hmma_mlp_kernel<<<dim3(128, 1), 128>>>(
                gm, bm, Wl, bl, q, qbs, out + (t - HALF) * FRM, OBS);
        }
    }
}